// round 14
// baseline (speedup 1.0000x reference)
#include <cuda_runtime.h>
#include <cuda_fp16.h>
#include <cstdint>
#include <math.h>

#define DM    768
#define DMLP  3072
#define NH    12
#define DH    64
#define BATCH 2
#define SEQ   2048
#define ROWS  (BATCH*SEQ)     /* 4096 */
#define QKVN  (3*DM)          /* 2304 */

// ---------------- scratch (static device globals; no allocation) -----------
__device__ __align__(16) __half g_x_h   [ROWS*DM];     // ln1 output
__device__ __align__(16) __half g_wqkv_h[DM*QKVN];     // packed QKV W [K,N]
__device__ float g_bqkv [QKVN];
__device__ __align__(16) __half g_qkv_h [ROWS*QKVN];   // Q|K|V per token
__device__ __align__(16) __half g_z_h   [ROWS*DM];     // attention output
__device__ float g_mid  [ROWS*DM];                     // resid_mid (fp32)
__device__ __align__(16) __half g_y_h   [ROWS*DM];     // ln2 output
__device__ __align__(16) __half g_h_h   [ROWS*DMLP];   // MLP hidden
__device__ __align__(16) __half g_wo_h  [DM*DM];       // W_O   fp16 [K,N]
__device__ __align__(16) __half g_win_h [DM*DMLP];     // W_in  fp16 [K,N]
__device__ __align__(16) __half g_wout_h[DMLP*DM];     // W_out fp16 [K,N]

// ======================= helpers ============================================
__device__ __forceinline__ uint32_t smem_u32(const void* p) {
    uint32_t a;
    asm("{ .reg .u64 t; cvta.to.shared.u64 t, %1; cvt.u32.u64 %0, t; }"
        : "=r"(a) : "l"(p));
    return a;
}
__device__ __forceinline__ float gelu_new(float v) {
    float v3 = v * v * v;
    return 0.5f * v * (1.f + tanhf(0.7978845608028654f * (v + 0.044715f * v3)));
}
__device__ __forceinline__ uint32_t pack_h2(float a, float b) {
    __half2 h = __floats2half2_rn(a, b);
    return *reinterpret_cast<uint32_t*>(&h);
}
__device__ __forceinline__ float ex2f(float x) {
    float y;
    asm("ex2.approx.f32 %0, %1;" : "=f"(y) : "f"(x));
    return y;
}
#define CP_ASYNC16(sa, gp) \
    asm volatile("cp.async.cg.shared.global [%0], [%1], 16;" :: "r"(sa), "l"(gp))
#define CP_COMMIT() asm volatile("cp.async.commit_group;" ::: "memory")
#define CP_WAIT(n)  asm volatile("cp.async.wait_group %0;" :: "n"(n) : "memory")

#define LDMX4(r, addr) \
    asm volatile("ldmatrix.sync.aligned.m8n8.x4.shared.b16 {%0,%1,%2,%3}, [%4];" \
        : "=r"((r)[0]), "=r"((r)[1]), "=r"((r)[2]), "=r"((r)[3]) : "r"(addr))
#define LDMX4T(r, addr) \
    asm volatile("ldmatrix.sync.aligned.m8n8.x4.trans.shared.b16 {%0,%1,%2,%3}, [%4];" \
        : "=r"((r)[0]), "=r"((r)[1]), "=r"((r)[2]), "=r"((r)[3]) : "r"(addr))

__device__ __forceinline__ void mma_f16(float* c, const uint32_t* a,
                                        uint32_t b0, uint32_t b1) {
    asm volatile(
        "mma.sync.aligned.m16n8k16.row.col.f32.f16.f16.f32 "
        "{%0,%1,%2,%3}, {%4,%5,%6,%7}, {%8,%9}, {%0,%1,%2,%3};\n"
        : "+f"(c[0]), "+f"(c[1]), "+f"(c[2]), "+f"(c[3])
        : "r"(a[0]), "r"(a[1]), "r"(a[2]), "r"(a[3]), "r"(b0), "r"(b1));
}

// ====== fp16 mma.sync GEMM (ldmatrix, BK=64): C[M,N] = A[M,K] @ B[K,N] ======
#define LDAH2 72
#define AH_STAGE2 (128*LDAH2)

template<int NJ> struct GemmHCfg {
    static const int BN      = NJ * 16;
    static const int LDBH_   = BN + 8;
    static const int B_STAGE = 64 * LDBH_;
    static const int STAGE   = AH_STAGE2 + B_STAGE;
    static const int SMEM    = 3 * STAGE * 2;
    static const int TBH     = BN / 32;
};

// EPI: 0 = bias->half, 1 = bias+gelu->half, 2 = bias+residual->float
template<int EPI, int NJ>
__global__ __launch_bounds__(256, 2)
void gemm_h(const __half* __restrict__ A, const __half* __restrict__ B,
            const float* __restrict__ bias, const float* __restrict__ R,
            void* __restrict__ Cout, int M, int N, int K) {
    typedef GemmHCfg<NJ> CFG;
    extern __shared__ __half smh[];
    const uint32_t sbase = smem_u32(smh);
    const int tid = threadIdx.x, lane = tid & 31, wid = tid >> 5;
    const int wm = wid & 3, wn = wid >> 2;
    const int bm = blockIdx.y * 128, bn = blockIdx.x * CFG::BN;
    const int niter = K >> 6;

    int ar[4], ac[4];
    #pragma unroll
    for (int t = 0; t < 4; t++) {
        int ci = tid + t * 256;
        ar[t] = ci >> 3;  ac[t] = (ci & 7) * 8;
    }
    int br[CFG::TBH], bc[CFG::TBH];
    #pragma unroll
    for (int t = 0; t < CFG::TBH; t++) {
        int ci = tid + t * 256;
        br[t] = ci / (CFG::BN / 8);
        bc[t] = (ci % (CFG::BN / 8)) * 8;
    }

    float acc[2][NJ][4];
    #pragma unroll
    for (int mi = 0; mi < 2; mi++)
        #pragma unroll
        for (int nj = 0; nj < NJ; nj++)
            #pragma unroll
            for (int r = 0; r < 4; r++) acc[mi][nj][r] = 0.f;

    auto issue = [&](int ks, int buf) {
        const int k0 = ks << 6;
        const uint32_t s0 = sbase + (uint32_t)buf * CFG::STAGE * 2u;
        #pragma unroll
        for (int t = 0; t < 4; t++)
            CP_ASYNC16(s0 + (uint32_t)(ar[t] * LDAH2 + ac[t]) * 2u,
                       A + (size_t)(bm + ar[t]) * K + k0 + ac[t]);
        const uint32_t s1 = s0 + AH_STAGE2 * 2u;
        #pragma unroll
        for (int t = 0; t < CFG::TBH; t++)
            CP_ASYNC16(s1 + (uint32_t)(br[t] * CFG::LDBH_ + bc[t]) * 2u,
                       B + (size_t)(k0 + br[t]) * N + bn + bc[t]);
        CP_COMMIT();
    };

    issue(0, 0);
    issue(1, 1);

    const int l15 = lane & 15, lhi = lane >> 4;
    const uint32_t aAddrBase = (uint32_t)(((wm * 32 + l15) * LDAH2 + lhi * 8) * 2);
    const uint32_t bAddrBase = (uint32_t)((l15 * CFG::LDBH_ + wn * (NJ * 8) + lhi * 8) * 2);

    for (int i = 0; i < niter; i++) {
        if (i + 1 < niter) { CP_WAIT(1); } else { CP_WAIT(0); }
        __syncthreads();
        if (i + 2 < niter) issue(i + 2, (i + 2) % 3);

        const uint32_t sA = sbase + (uint32_t)((i % 3) * CFG::STAGE) * 2u;
        const uint32_t sB = sA + AH_STAGE2 * 2u;

        #pragma unroll
        for (int kk = 0; kk < 4; kk++) {
            uint32_t a[2][4];
            #pragma unroll
            for (int mi = 0; mi < 2; mi++)
                LDMX4(a[mi], sA + aAddrBase + (uint32_t)((mi * 16 * LDAH2 + kk * 16) * 2));
            #pragma unroll
            for (int nj2 = 0; nj2 < NJ / 2; nj2++) {
                uint32_t bf[4];
                LDMX4T(bf, sB + bAddrBase + (uint32_t)((kk * 16 * CFG::LDBH_ + nj2 * 16) * 2));
                #pragma unroll
                for (int hh = 0; hh < 2; hh++) {
                    #pragma unroll
                    for (int mi = 0; mi < 2; mi++)
                        mma_f16(acc[mi][nj2 * 2 + hh], a[mi], bf[hh * 2], bf[hh * 2 + 1]);
                }
            }
        }
    }

    #pragma unroll
    for (int mi = 0; mi < 2; mi++) {
        const int row0 = bm + wm * 32 + mi * 16 + (lane >> 2);
        #pragma unroll
        for (int nj = 0; nj < NJ; nj++) {
            const int col0 = bn + wn * (NJ * 8) + nj * 8 + (lane & 3) * 2;
            const float b0 = bias[col0], b1 = bias[col0 + 1];
            #pragma unroll
            for (int hh = 0; hh < 2; hh++) {
                const int row = row0 + hh * 8;
                float v0 = acc[mi][nj][hh * 2 + 0] + b0;
                float v1 = acc[mi][nj][hh * 2 + 1] + b1;
                size_t g = (size_t)row * N + col0;
                if (EPI == 0) {
                    *(__half2*)((__half*)Cout + g) = __floats2half2_rn(v0, v1);
                } else if (EPI == 1) {
                    *(__half2*)((__half*)Cout + g) =
                        __floats2half2_rn(gelu_new(v0), gelu_new(v1));
                } else {
                    float2 rv = *(const float2*)(R + g);
                    float2 o; o.x = v0 + rv.x; o.y = v1 + rv.y;
                    *(float2*)((float*)Cout + g) = o;
                }
            }
        }
    }
}

// ---------------- layernorm: 4 rows/block, 64 thr/row, float4, 1 pass -------
__global__ __launch_bounds__(256)
void ln4_h(const float* __restrict__ in, const float* __restrict__ w,
           const float* __restrict__ b, __half* __restrict__ out) {
    const int tid = threadIdx.x;
    const int rloc = tid >> 6;
    const int t    = tid & 63;
    const int row  = blockIdx.x * 4 + rloc;
    const int lane = tid & 31;
    const int wIdx = (tid >> 5) & 1;

    const float4* xp = (const float4*)(in + (size_t)row * DM);
    float4 v[3];
    float s = 0.f, ss = 0.f;
    #pragma unroll
    for (int k = 0; k < 3; k++) {
        v[k] = xp[t + k * 64];
        s  += v[k].x + v[k].y + v[k].z + v[k].w;
        ss += v[k].x * v[k].x + v[k].y * v[k].y + v[k].z * v[k].z + v[k].w * v[k].w;
    }
    #pragma unroll
    for (int o = 16; o; o >>= 1) {
        s  += __shfl_xor_sync(0xffffffffu, s,  o);
        ss += __shfl_xor_sync(0xffffffffu, ss, o);
    }
    __shared__ float sb[4][2], qb[4][2];
    if (lane == 0) { sb[rloc][wIdx] = s; qb[rloc][wIdx] = ss; }
    __syncthreads();
    s  = sb[rloc][0] + sb[rloc][1];
    ss = qb[rloc][0] + qb[rloc][1];
    float mean = s * (1.f / DM);
    float inv  = rsqrtf(ss * (1.f / DM) - mean * mean + 1e-5f);

    const float4* wp = (const float4*)w;
    const float4* bp = (const float4*)b;
    __half2* op = (__half2*)(out + (size_t)row * DM);
    #pragma unroll
    for (int k = 0; k < 3; k++) {
        float4 wv = wp[t + k * 64], bv = bp[t + k * 64];
        float o0 = (v[k].x - mean) * inv * wv.x + bv.x;
        float o1 = (v[k].y - mean) * inv * wv.y + bv.y;
        float o2 = (v[k].z - mean) * inv * wv.z + bv.z;
        float o3 = (v[k].w - mean) * inv * wv.w + bv.w;
        op[(t + k * 64) * 2]     = __floats2half2_rn(o0, o1);
        op[(t + k * 64) * 2 + 1] = __floats2half2_rn(o2, o3);
    }
}

// ---------------- merged weight prep (vectorized) ----------------------------
__global__ void prep_weights(const float* __restrict__ WQ, const float* __restrict__ WK,
                             const float* __restrict__ WV, const float* __restrict__ WO,
                             const float* __restrict__ Win, const float* __restrict__ Wout,
                             const float* __restrict__ bQ, const float* __restrict__ bK,
                             const float* __restrict__ bV,
                             __half* __restrict__ Wqkv, __half* __restrict__ Wo_h,
                             __half* __restrict__ Win_h, __half* __restrict__ Wout_h,
                             float* __restrict__ bias) {
    int idx = blockIdx.x * 256 + threadIdx.x;
    if (idx < DM * DM) {
        float4 wi = ((const float4*)Win)[idx];
        float4 wo = ((const float4*)Wout)[idx];
        ((__half2*)Win_h)[idx * 2]      = __floats2half2_rn(wi.x, wi.y);
        ((__half2*)Win_h)[idx * 2 + 1]  = __floats2half2_rn(wi.z, wi.w);
        ((__half2*)Wout_h)[idx * 2]     = __floats2half2_rn(wo.x, wo.y);
        ((__half2*)Wout_h)[idx * 2 + 1] = __floats2half2_rn(wo.z, wo.w);
        Wo_h[idx] = __float2half_rn(WO[idx]);
        int k = idx / DM, n = idx % DM;
        int h = n >> 6, e = n & 63;
        int src = h * (DM * DH) + k * DH + e;
        Wqkv[(size_t)k * QKVN + n]          = __float2half_rn(WQ[src]);
        Wqkv[(size_t)k * QKVN + DM + n]     = __float2half_rn(WK[src]);
        Wqkv[(size_t)k * QKVN + 2 * DM + n] = __float2half_rn(WV[src]);
    }
    if (idx < DM) {
        bias[idx]          = bQ[idx];
        bias[DM + idx]     = bK[idx];
        bias[2 * DM + idx] = bV[idx];
    }
}

// ============== flash attention via fp16 mma.sync (causal, cp.async) ========
// 3-buffer K/V ring; 1 sync per K-tile; softmax in log2 domain (ex2.approx).
#define LDH 72
#define AK_OFF (128*LDH)
#define AV_OFF (AK_OFF + 3*64*LDH)
#define ATTNH_SMEM ((AV_OFF + 3*64*LDH)*2)

__global__ __launch_bounds__(256, 2)
void attn_h(const __half* __restrict__ QKV, __half* __restrict__ Z) {
    extern __shared__ __half smh[];
    const uint32_t sbase = smem_u32(smh);

    const int tid = threadIdx.x, lane = tid & 31, wid = tid >> 5;
    const int r = lane >> 2, c = lane & 3;
    const int l15 = lane & 15, lhi = lane >> 4;
    const int qt = gridDim.x - 1 - blockIdx.x;
    const int qt0 = qt * 128;
    const int h = blockIdx.y, b = blockIdx.z;

    const __half* qbase = QKV + ((size_t)(b * SEQ + qt0)) * QKVN + h * DH;
    const __half* kbase = QKV + ((size_t)b * SEQ) * QKVN + DM     + h * DH;
    const __half* vbase = QKV + ((size_t)b * SEQ) * QKVN + 2 * DM + h * DH;

    const int ntiles = qt0 / 64 + 2;

    auto issue_kv = [&](int kt, int buf) {
        const __half* kb = kbase + (size_t)(kt * 64) * QKVN;
        const __half* vb = vbase + (size_t)(kt * 64) * QKVN;
        const uint32_t ks = sbase + (uint32_t)(AK_OFF + buf * 64 * LDH) * 2u;
        const uint32_t vs = sbase + (uint32_t)(AV_OFF + buf * 64 * LDH) * 2u;
        #pragma unroll
        for (int t = 0; t < 2; t++) {
            int ci = tid + t * 256;
            int row = ci >> 3, ch = (ci & 7) * 8;
            CP_ASYNC16(ks + (uint32_t)(row * LDH + ch) * 2u,
                       kb + (size_t)row * QKVN + ch);
            CP_ASYNC16(vs + (uint32_t)(row * LDH + ch) * 2u,
                       vb + (size_t)row * QKVN + ch);
        }
        CP_COMMIT();
    };

    {
        #pragma unroll
        for (int t = 0; t < 4; t++) {
            int ci = tid + t * 256;
            int row = ci >> 3, ch = (ci & 7) * 8;
            CP_ASYNC16(sbase + (uint32_t)(row * LDH + ch) * 2u,
                       qbase + (size_t)row * QKVN + ch);
        }
        const uint32_t ks = sbase + (uint32_t)AK_OFF * 2u;
        const uint32_t vs = sbase + (uint32_t)AV_OFF * 2u;
        #pragma unroll
        for (int t = 0; t < 2; t++) {
            int ci = tid + t * 256;
            int row = ci >> 3, ch = (ci & 7) * 8;
            CP_ASYNC16(ks + (uint32_t)(row * LDH + ch) * 2u,
                       kbase + (size_t)row * QKVN + ch);
            CP_ASYNC16(vs + (uint32_t)(row * LDH + ch) * 2u,
                       vbase + (size_t)row * QKVN + ch);
        }
        CP_COMMIT();
    }
    if (ntiles > 1) issue_kv(1, 1);

    float o[8][4];
    #pragma unroll
    for (int nj = 0; nj < 8; nj++)
        #pragma unroll
        for (int t = 0; t < 4; t++) o[nj][t] = 0.f;
    float m0 = -1e30f, m1 = -1e30f, l0 = 0.f, l1 = 0.f;

    const int q0g = qt0 + wid * 16 + r;
    const int qmax_warp = qt0 + wid * 16 + 15;

    uint32_t qa[4][4];

    for (int kt = 0; kt < ntiles; kt++) {
        if (kt + 1 < ntiles) { CP_WAIT(1); } else { CP_WAIT(0); }
        __syncthreads();
        if (kt + 2 < ntiles) issue_kv(kt + 2, (kt + 2) % 3);

        if (kt == 0) {
            const uint32_t qaddr = sbase + (uint32_t)(((wid * 16 + l15) * LDH + lhi * 8) * 2);
            __half2 sc = __floats2half2_rn(0.18033688f, 0.18033688f);
            #pragma unroll
            for (int kk = 0; kk < 4; kk++) {
                LDMX4(qa[kk], qaddr + (uint32_t)(kk * 16 * 2));
                #pragma unroll
                for (int j = 0; j < 4; j++) {
                    __half2 v = *reinterpret_cast<__half2*>(&qa[kk][j]);
                    v = __hmul2(v, sc);
                    qa[kk][j] = *reinterpret_cast<uint32_t*>(&v);
                }
            }
        }

        if (kt * 64 <= qmax_warp) {
            const int buf = kt % 3;
            const uint32_t Kb = sbase + (uint32_t)(AK_OFF + buf * 64 * LDH) * 2u;
            const uint32_t Vb = sbase + (uint32_t)(AV_OFF + buf * 64 * LDH) * 2u;

            float s[8][4];
            #pragma unroll
            for (int nj = 0; nj < 8; nj++)
                #pragma unroll
                for (int t = 0; t < 4; t++) s[nj][t] = 0.f;

            const int g = lane >> 3;
            #pragma unroll
            for (int g2 = 0; g2 < 4; g2++) {
                const uint32_t rowb = Kb +
                    (uint32_t)(((16 * g2 + (g >> 1) * 8 + (lane & 7)) * LDH) * 2);
                #pragma unroll
                for (int kk = 0; kk < 4; kk++) {
                    uint32_t bk[4];
                    LDMX4(bk, rowb + (uint32_t)((kk * 16 + (g & 1) * 8) * 2));
                    mma_f16(s[2 * g2],     qa[kk], bk[0], bk[1]);
                    mma_f16(s[2 * g2 + 1], qa[kk], bk[2], bk[3]);
                }
            }

            if (kt * 64 + 63 > qt0 + wid * 16) {
                #pragma unroll
                for (int nj = 0; nj < 8; nj++) {
                    int k0c = kt * 64 + nj * 8 + c * 2;
                    if (k0c     > q0g)     s[nj][0] = -1e30f;
                    if (k0c + 1 > q0g)     s[nj][1] = -1e30f;
                    if (k0c     > q0g + 8) s[nj][2] = -1e30f;
                    if (k0c + 1 > q0g + 8) s[nj][3] = -1e30f;
                }
            }

            float mt0 = -1e30f, mt1 = -1e30f;
            #pragma unroll
            for (int nj = 0; nj < 8; nj++) {
                mt0 = fmaxf(mt0, fmaxf(s[nj][0], s[nj][1]));
                mt1 = fmaxf(mt1, fmaxf(s[nj][2], s[nj][3]));
            }
            mt0 = fmaxf(mt0, __shfl_xor_sync(0xffffffffu, mt0, 1));
            mt0 = fmaxf(mt0, __shfl_xor_sync(0xffffffffu, mt0, 2));
            mt1 = fmaxf(mt1, __shfl_xor_sync(0xffffffffu, mt1, 1));
            mt1 = fmaxf(mt1, __shfl_xor_sync(0xffffffffu, mt1, 2));

            float mn0 = fmaxf(m0, mt0), mn1 = fmaxf(m1, mt1);
            float cr0 = ex2f(m0 - mn0), cr1 = ex2f(m1 - mn1);
            float ls0 = 0.f, ls1 = 0.f;
            #pragma unroll
            for (int nj = 0; nj < 8; nj++) {
                s[nj][0] = ex2f(s[nj][0] - mn0);
                s[nj][1] = ex2f(s[nj][1] - mn0);
                s[nj][2] = ex2f(s[nj][2] - mn1);
                s[nj][3] = ex2f(s[nj][3] - mn1);
                ls0 += s[nj][0] + s[nj][1];
                ls1 += s[nj][2] + s[nj][3];
            }
            ls0 += __shfl_xor_sync(0xffffffffu, ls0, 1);
            ls0 += __shfl_xor_sync(0xffffffffu, ls0, 2);
            ls1 += __shfl_xor_sync(0xffffffffu, ls1, 1);
            ls1 += __shfl_xor_sync(0xffffffffu, ls1, 2);
            l0 = l0 * cr0 + ls0;
            l1 = l1 * cr1 + ls1;
            m0 = mn0; m1 = mn1;
            #pragma unroll
            for (int nj = 0; nj < 8; nj++) {
                o[nj][0] *= cr0; o[nj][1] *= cr0;
                o[nj][2] *= cr1; o[nj][3] *= cr1;
            }

            #pragma unroll
            for (int kk = 0; kk < 4; kk++) {
                uint32_t pa[4];
                pa[0] = pack_h2(s[2 * kk][0],     s[2 * kk][1]);
                pa[1] = pack_h2(s[2 * kk][2],     s[2 * kk][3]);
                pa[2] = pack_h2(s[2 * kk + 1][0], s[2 * kk + 1][1]);
                pa[3] = pack_h2(s[2 * kk + 1][2], s[2 * kk + 1][3]);
                const uint32_t rowb = Vb + (uint32_t)(((kk * 16 + l15) * LDH + lhi * 8) * 2);
                #pragma unroll
                for (int nj2 = 0; nj2 < 4; nj2++) {
                    uint32_t bv[4];
                    LDMX4T(bv, rowb + (uint32_t)((nj2 * 16) * 2));
                    mma_f16(o[2 * nj2],     pa, bv[0], bv[1]);
                    mma_f16(o[2 * nj2 + 1], pa, bv[2], bv[3]);
                }
            }
        }
    }

    float inv0 = 1.f / l0, inv1 = 1.f / l1;
    #pragma unroll
    for (int nj = 0; nj < 8; nj++) {
        int col = h * DH + nj * 8 + c * 2;
        size_t g0 = (size_t)(b * SEQ + q0g) * DM + col;
        size_t g1 = (size_t)(b * SEQ + q0g + 8) * DM + col;
        *(__half2*)(Z + g0) = __floats2half2_rn(o[nj][0] * inv0, o[nj][1] * inv0);
        *(__half2*)(Z + g1) = __floats2half2_rn(o[nj][2] * inv1, o[nj][3] * inv1);
    }
}

// ---------------- launch -----------------------------------------------------
extern "C" void kernel_launch(void* const* d_in, const int* in_sizes, int n_in,
                              void* d_out, int out_size) {
    const float* resid_pre = (const float*)d_in[0];
    const float* W_Q   = (const float*)d_in[1];
    const float* b_Q   = (const float*)d_in[2];
    const float* W_K   = (const float*)d_in[3];
    const float* b_K   = (const float*)d_in[4];
    const float* W_V   = (const float*)d_in[5];
    const float* b_V   = (const float*)d_in[6];
    const float* W_O   = (const float*)d_in[7];
    const float* b_O   = (const float*)d_in[8];
    const float* ln1_w = (const float*)d_in[9];
    const float* ln1_b = (const float*)d_in[10];
    const float* ln2_w = (const float*)d_in[11];
    const float* ln2_b = (const float*)d_in[12];
    const float* W_in  = (const float*)d_in[13];
    const float* b_in  = (const float*)d_in[14];
    const float* W_out = (const float*)d_in[15];
    const float* b_out = (const float*)d_in[16];
    float* out = (float*)d_out;

    float *pbqkv, *pmid;
    __half *px_h, *pwqkv_h, *pqkv_h, *pz_h, *py_h, *ph_h, *pwo_h, *pwin_h, *pwout_h;
    cudaGetSymbolAddress((void**)&px_h,    g_x_h);
    cudaGetSymbolAddress((void**)&pwqkv_h, g_wqkv_h);
    cudaGetSymbolAddress((void**)&pbqkv,   g_bqkv);
    cudaGetSymbolAddress((void**)&pqkv_h,  g_qkv_h);
    cudaGetSymbolAddress((void**)&pz_h,    g_z_h);
    cudaGetSymbolAddress((void**)&pmid,    g_mid);
    cudaGetSymbolAddress((void**)&py_h,    g_y_h);
    cudaGetSymbolAddress((void**)&ph_h,    g_h_h);
    cudaGetSymbolAddress((void**)&pwo_h,   g_wo_h);
    cudaGetSymbolAddress((void**)&pwin_h,  g_win_h);
    cudaGetSymbolAddress((void**)&pwout_h, g_wout_h);

    cudaFuncSetAttribute((const void*)gemm_h<0,8>, cudaFuncAttributeMaxDynamicSharedMemorySize, GemmHCfg<8>::SMEM);
    cudaFuncSetAttribute((const void*)gemm_h<1,8>, cudaFuncAttributeMaxDynamicSharedMemorySize, GemmHCfg<8>::SMEM);
    cudaFuncSetAttribute((const void*)gemm_h<2,8>, cudaFuncAttributeMaxDynamicSharedMemorySize, GemmHCfg<8>::SMEM);
    cudaFuncSetAttribute((const void*)gemm_h<2,4>, cudaFuncAttributeMaxDynamicSharedMemorySize, GemmHCfg<4>::SMEM);
    cudaFuncSetAttribute((const void*)attn_h,      cudaFuncAttributeMaxDynamicSharedMemorySize, ATTNH_SMEM);

    prep_weights<<<(DM * DM + 255) / 256, 256>>>(
        W_Q, W_K, W_V, W_O, W_in, W_out, b_Q, b_K, b_V,
        pwqkv_h, pwo_h, pwin_h, pwout_h, pbqkv);

    ln4_h<<<ROWS / 4, 256>>>(resid_pre, ln1_w, ln1_b, px_h);
    gemm_h<0,8><<<dim3(QKVN / 128, ROWS / 128), 256, GemmHCfg<8>::SMEM>>>(
        px_h, pwqkv_h, pbqkv, nullptr, pqkv_h, ROWS, QKVN, DM);
    attn_h<<<dim3(SEQ / 128, NH, BATCH), 256, ATTNH_SMEM>>>(pqkv_h, pz_h);
    // O-proj: short K (12 iters) -> BN=64 for wave fill
    gemm_h<2,4><<<dim3(DM / 64, ROWS / 128), 256, GemmHCfg<4>::SMEM>>>(
        pz_h, pwo_h, b_O, resid_pre, pmid, ROWS, DM, DM);
    ln4_h<<<ROWS / 4, 256>>>(pmid, ln2_w, ln2_b, py_h);
    gemm_h<1,8><<<dim3(DMLP / 128, ROWS / 128), 256, GemmHCfg<8>::SMEM>>>(
        py_h, pwin_h, b_in, nullptr, ph_h, ROWS, DMLP, DM);
    // MLP-out: long K (48 iters) -> BN=128 to halve L2 tile traffic
    gemm_h<2,8><<<dim3(DM / 128, ROWS / 128), 256, GemmHCfg<8>::SMEM>>>(
        ph_h, pwout_h, b_out, pmid, out, ROWS, DM, DMLP);
}

// round 15
// speedup vs baseline: 1.0145x; 1.0145x over previous
#include <cuda_runtime.h>
#include <cuda_fp16.h>
#include <cstdint>
#include <math.h>

#define DM    768
#define DMLP  3072
#define NH    12
#define DH    64
#define BATCH 2
#define SEQ   2048
#define ROWS  (BATCH*SEQ)     /* 4096 */
#define QKVN  (3*DM)          /* 2304 */

// ---------------- scratch (static device globals; no allocation) -----------
__device__ __align__(16) __half g_x_h   [ROWS*DM];     // ln1 output
__device__ __align__(16) __half g_wqkv_h[DM*QKVN];     // packed QKV W [K,N]
__device__ float g_bqkv [QKVN];
__device__ __align__(16) __half g_qkv_h [ROWS*QKVN];   // Q|K|V per token
__device__ __align__(16) __half g_z_h   [ROWS*DM];     // attention output
__device__ float g_mid  [ROWS*DM];                     // resid_mid (fp32)
__device__ __align__(16) __half g_y_h   [ROWS*DM];     // ln2 output
__device__ __align__(16) __half g_h_h   [ROWS*DMLP];   // MLP hidden
__device__ __align__(16) __half g_wo_h  [DM*DM];       // W_O   fp16 [K,N]
__device__ __align__(16) __half g_win_h [DM*DMLP];     // W_in  fp16 [K,N]
__device__ __align__(16) __half g_wout_h[DMLP*DM];     // W_out fp16 [K,N]

// ======================= helpers ============================================
__device__ __forceinline__ uint32_t smem_u32(const void* p) {
    uint32_t a;
    asm("{ .reg .u64 t; cvta.to.shared.u64 t, %1; cvt.u32.u64 %0, t; }"
        : "=r"(a) : "l"(p));
    return a;
}
__device__ __forceinline__ float gelu_new(float v) {
    float v3 = v * v * v;
    return 0.5f * v * (1.f + tanhf(0.7978845608028654f * (v + 0.044715f * v3)));
}
__device__ __forceinline__ uint32_t pack_h2(float a, float b) {
    __half2 h = __floats2half2_rn(a, b);
    return *reinterpret_cast<uint32_t*>(&h);
}
__device__ __forceinline__ float ex2f(float x) {
    float y;
    asm("ex2.approx.f32 %0, %1;" : "=f"(y) : "f"(x));
    return y;
}
#define CP_ASYNC16(sa, gp) \
    asm volatile("cp.async.cg.shared.global [%0], [%1], 16;" :: "r"(sa), "l"(gp))
#define CP_COMMIT() asm volatile("cp.async.commit_group;" ::: "memory")
#define CP_WAIT(n)  asm volatile("cp.async.wait_group %0;" :: "n"(n) : "memory")

#define LDMX4(r, addr) \
    asm volatile("ldmatrix.sync.aligned.m8n8.x4.shared.b16 {%0,%1,%2,%3}, [%4];" \
        : "=r"((r)[0]), "=r"((r)[1]), "=r"((r)[2]), "=r"((r)[3]) : "r"(addr))
#define LDMX4T(r, addr) \
    asm volatile("ldmatrix.sync.aligned.m8n8.x4.trans.shared.b16 {%0,%1,%2,%3}, [%4];" \
        : "=r"((r)[0]), "=r"((r)[1]), "=r"((r)[2]), "=r"((r)[3]) : "r"(addr))

__device__ __forceinline__ void mma_f16(float* c, const uint32_t* a,
                                        uint32_t b0, uint32_t b1) {
    asm volatile(
        "mma.sync.aligned.m16n8k16.row.col.f32.f16.f16.f32 "
        "{%0,%1,%2,%3}, {%4,%5,%6,%7}, {%8,%9}, {%0,%1,%2,%3};\n"
        : "+f"(c[0]), "+f"(c[1]), "+f"(c[2]), "+f"(c[3])
        : "r"(a[0]), "r"(a[1]), "r"(a[2]), "r"(a[3]), "r"(b0), "r"(b1));
}

// ====== fp16 mma.sync GEMM (ldmatrix, BK=64): C[M,N] = A[M,K] @ B[K,N] ======
#define LDAH2 72
#define AH_STAGE2 (128*LDAH2)

template<int NJ, int ST> struct GemmHCfg {
    static const int BN      = NJ * 16;
    static const int LDBH_   = BN + 8;
    static const int B_STAGE = 64 * LDBH_;
    static const int STAGE   = AH_STAGE2 + B_STAGE;
    static const int SMEM    = ST * STAGE * 2;
    static const int TBH     = BN / 32;
};

// EPI: 0 = bias->half, 1 = bias+gelu->half, 2 = bias+residual->float
template<int EPI, int NJ, int ST>
__global__ __launch_bounds__(256, 2)
void gemm_h(const __half* __restrict__ A, const __half* __restrict__ B,
            const float* __restrict__ bias, const float* __restrict__ R,
            void* __restrict__ Cout, int M, int N, int K) {
    typedef GemmHCfg<NJ, ST> CFG;
    extern __shared__ __half smh[];
    const uint32_t sbase = smem_u32(smh);
    const int tid = threadIdx.x, lane = tid & 31, wid = tid >> 5;
    const int wm = wid & 3, wn = wid >> 2;
    const int bm = blockIdx.y * 128, bn = blockIdx.x * CFG::BN;
    const int niter = K >> 6;

    int ar[4], ac[4];
    #pragma unroll
    for (int t = 0; t < 4; t++) {
        int ci = tid + t * 256;
        ar[t] = ci >> 3;  ac[t] = (ci & 7) * 8;
    }
    int br[CFG::TBH], bc[CFG::TBH];
    #pragma unroll
    for (int t = 0; t < CFG::TBH; t++) {
        int ci = tid + t * 256;
        br[t] = ci / (CFG::BN / 8);
        bc[t] = (ci % (CFG::BN / 8)) * 8;
    }

    float acc[2][NJ][4];
    #pragma unroll
    for (int mi = 0; mi < 2; mi++)
        #pragma unroll
        for (int nj = 0; nj < NJ; nj++)
            #pragma unroll
            for (int r = 0; r < 4; r++) acc[mi][nj][r] = 0.f;

    auto issue = [&](int ks, int buf) {
        const int k0 = ks << 6;
        const uint32_t s0 = sbase + (uint32_t)buf * CFG::STAGE * 2u;
        #pragma unroll
        for (int t = 0; t < 4; t++)
            CP_ASYNC16(s0 + (uint32_t)(ar[t] * LDAH2 + ac[t]) * 2u,
                       A + (size_t)(bm + ar[t]) * K + k0 + ac[t]);
        const uint32_t s1 = s0 + AH_STAGE2 * 2u;
        #pragma unroll
        for (int t = 0; t < CFG::TBH; t++)
            CP_ASYNC16(s1 + (uint32_t)(br[t] * CFG::LDBH_ + bc[t]) * 2u,
                       B + (size_t)(k0 + br[t]) * N + bn + bc[t]);
        CP_COMMIT();
    };

    #pragma unroll
    for (int p = 0; p < ST - 1; p++)
        if (p < niter) issue(p, p);

    const int l15 = lane & 15, lhi = lane >> 4;
    const uint32_t aAddrBase = (uint32_t)(((wm * 32 + l15) * LDAH2 + lhi * 8) * 2);
    const uint32_t bAddrBase = (uint32_t)((l15 * CFG::LDBH_ + wn * (NJ * 8) + lhi * 8) * 2);

    for (int i = 0; i < niter; i++) {
        if (i + ST - 2 < niter) { CP_WAIT(ST - 2); } else { CP_WAIT(0); }
        __syncthreads();
        if (i + ST - 1 < niter) issue(i + ST - 1, (i + ST - 1) % ST);

        const uint32_t sA = sbase + (uint32_t)((i % ST) * CFG::STAGE) * 2u;
        const uint32_t sB = sA + AH_STAGE2 * 2u;

        #pragma unroll
        for (int kk = 0; kk < 4; kk++) {
            uint32_t a[2][4];
            #pragma unroll
            for (int mi = 0; mi < 2; mi++)
                LDMX4(a[mi], sA + aAddrBase + (uint32_t)((mi * 16 * LDAH2 + kk * 16) * 2));
            #pragma unroll
            for (int nj2 = 0; nj2 < NJ / 2; nj2++) {
                uint32_t bf[4];
                LDMX4T(bf, sB + bAddrBase + (uint32_t)((kk * 16 * CFG::LDBH_ + nj2 * 16) * 2));
                #pragma unroll
                for (int hh = 0; hh < 2; hh++) {
                    #pragma unroll
                    for (int mi = 0; mi < 2; mi++)
                        mma_f16(acc[mi][nj2 * 2 + hh], a[mi], bf[hh * 2], bf[hh * 2 + 1]);
                }
            }
        }
    }

    #pragma unroll
    for (int mi = 0; mi < 2; mi++) {
        const int row0 = bm + wm * 32 + mi * 16 + (lane >> 2);
        #pragma unroll
        for (int nj = 0; nj < NJ; nj++) {
            const int col0 = bn + wn * (NJ * 8) + nj * 8 + (lane & 3) * 2;
            const float b0 = bias[col0], b1 = bias[col0 + 1];
            #pragma unroll
            for (int hh = 0; hh < 2; hh++) {
                const int row = row0 + hh * 8;
                float v0 = acc[mi][nj][hh * 2 + 0] + b0;
                float v1 = acc[mi][nj][hh * 2 + 1] + b1;
                size_t g = (size_t)row * N + col0;
                if (EPI == 0) {
                    *(__half2*)((__half*)Cout + g) = __floats2half2_rn(v0, v1);
                } else if (EPI == 1) {
                    *(__half2*)((__half*)Cout + g) =
                        __floats2half2_rn(gelu_new(v0), gelu_new(v1));
                } else {
                    float2 rv = *(const float2*)(R + g);
                    float2 o; o.x = v0 + rv.x; o.y = v1 + rv.y;
                    *(float2*)((float*)Cout + g) = o;
                }
            }
        }
    }
}

// ---------------- layernorm: 4 rows/block, 64 thr/row, float4, 1 pass -------
__global__ __launch_bounds__(256)
void ln4_h(const float* __restrict__ in, const float* __restrict__ w,
           const float* __restrict__ b, __half* __restrict__ out) {
    const int tid = threadIdx.x;
    const int rloc = tid >> 6;
    const int t    = tid & 63;
    const int row  = blockIdx.x * 4 + rloc;
    const int lane = tid & 31;
    const int wIdx = (tid >> 5) & 1;

    const float4* xp = (const float4*)(in + (size_t)row * DM);
    float4 v[3];
    float s = 0.f, ss = 0.f;
    #pragma unroll
    for (int k = 0; k < 3; k++) {
        v[k] = xp[t + k * 64];
        s  += v[k].x + v[k].y + v[k].z + v[k].w;
        ss += v[k].x * v[k].x + v[k].y * v[k].y + v[k].z * v[k].z + v[k].w * v[k].w;
    }
    #pragma unroll
    for (int o = 16; o; o >>= 1) {
        s  += __shfl_xor_sync(0xffffffffu, s,  o);
        ss += __shfl_xor_sync(0xffffffffu, ss, o);
    }
    __shared__ float sb[4][2], qb[4][2];
    if (lane == 0) { sb[rloc][wIdx] = s; qb[rloc][wIdx] = ss; }
    __syncthreads();
    s  = sb[rloc][0] + sb[rloc][1];
    ss = qb[rloc][0] + qb[rloc][1];
    float mean = s * (1.f / DM);
    float inv  = rsqrtf(ss * (1.f / DM) - mean * mean + 1e-5f);

    const float4* wp = (const float4*)w;
    const float4* bp = (const float4*)b;
    __half2* op = (__half2*)(out + (size_t)row * DM);
    #pragma unroll
    for (int k = 0; k < 3; k++) {
        float4 wv = wp[t + k * 64], bv = bp[t + k * 64];
        float o0 = (v[k].x - mean) * inv * wv.x + bv.x;
        float o1 = (v[k].y - mean) * inv * wv.y + bv.y;
        float o2 = (v[k].z - mean) * inv * wv.z + bv.z;
        float o3 = (v[k].w - mean) * inv * wv.w + bv.w;
        op[(t + k * 64) * 2]     = __floats2half2_rn(o0, o1);
        op[(t + k * 64) * 2 + 1] = __floats2half2_rn(o2, o3);
    }
}

// ---------------- merged weight prep (vectorized) ----------------------------
__global__ void prep_weights(const float* __restrict__ WQ, const float* __restrict__ WK,
                             const float* __restrict__ WV, const float* __restrict__ WO,
                             const float* __restrict__ Win, const float* __restrict__ Wout,
                             const float* __restrict__ bQ, const float* __restrict__ bK,
                             const float* __restrict__ bV,
                             __half* __restrict__ Wqkv, __half* __restrict__ Wo_h,
                             __half* __restrict__ Win_h, __half* __restrict__ Wout_h,
                             float* __restrict__ bias) {
    int idx = blockIdx.x * 256 + threadIdx.x;
    if (idx < DM * DM) {
        float4 wi = ((const float4*)Win)[idx];
        float4 wo = ((const float4*)Wout)[idx];
        ((__half2*)Win_h)[idx * 2]      = __floats2half2_rn(wi.x, wi.y);
        ((__half2*)Win_h)[idx * 2 + 1]  = __floats2half2_rn(wi.z, wi.w);
        ((__half2*)Wout_h)[idx * 2]     = __floats2half2_rn(wo.x, wo.y);
        ((__half2*)Wout_h)[idx * 2 + 1] = __floats2half2_rn(wo.z, wo.w);
        Wo_h[idx] = __float2half_rn(WO[idx]);
        int k = idx / DM, n = idx % DM;
        int h = n >> 6, e = n & 63;
        int src = h * (DM * DH) + k * DH + e;
        Wqkv[(size_t)k * QKVN + n]          = __float2half_rn(WQ[src]);
        Wqkv[(size_t)k * QKVN + DM + n]     = __float2half_rn(WK[src]);
        Wqkv[(size_t)k * QKVN + 2 * DM + n] = __float2half_rn(WV[src]);
    }
    if (idx < DM) {
        bias[idx]          = bQ[idx];
        bias[DM + idx]     = bK[idx];
        bias[2 * DM + idx] = bV[idx];
    }
}

// ============== flash attention via fp16 mma.sync (causal, cp.async) ========
// 3-buffer K/V ring; 1 sync per K-tile; softmax in log2 domain (ex2.approx).
#define LDH 72
#define AK_OFF (128*LDH)
#define AV_OFF (AK_OFF + 3*64*LDH)
#define ATTNH_SMEM ((AV_OFF + 3*64*LDH)*2)

__global__ __launch_bounds__(256, 2)
void attn_h(const __half* __restrict__ QKV, __half* __restrict__ Z) {
    extern __shared__ __half smh[];
    const uint32_t sbase = smem_u32(smh);

    const int tid = threadIdx.x, lane = tid & 31, wid = tid >> 5;
    const int r = lane >> 2, c = lane & 3;
    const int l15 = lane & 15, lhi = lane >> 4;
    const int qt = gridDim.x - 1 - blockIdx.x;
    const int qt0 = qt * 128;
    const int h = blockIdx.y, b = blockIdx.z;

    const __half* qbase = QKV + ((size_t)(b * SEQ + qt0)) * QKVN + h * DH;
    const __half* kbase = QKV + ((size_t)b * SEQ) * QKVN + DM     + h * DH;
    const __half* vbase = QKV + ((size_t)b * SEQ) * QKVN + 2 * DM + h * DH;

    const int ntiles = qt0 / 64 + 2;

    auto issue_kv = [&](int kt, int buf) {
        const __half* kb = kbase + (size_t)(kt * 64) * QKVN;
        const __half* vb = vbase + (size_t)(kt * 64) * QKVN;
        const uint32_t ks = sbase + (uint32_t)(AK_OFF + buf * 64 * LDH) * 2u;
        const uint32_t vs = sbase + (uint32_t)(AV_OFF + buf * 64 * LDH) * 2u;
        #pragma unroll
        for (int t = 0; t < 2; t++) {
            int ci = tid + t * 256;
            int row = ci >> 3, ch = (ci & 7) * 8;
            CP_ASYNC16(ks + (uint32_t)(row * LDH + ch) * 2u,
                       kb + (size_t)row * QKVN + ch);
            CP_ASYNC16(vs + (uint32_t)(row * LDH + ch) * 2u,
                       vb + (size_t)row * QKVN + ch);
        }
        CP_COMMIT();
    };

    {
        #pragma unroll
        for (int t = 0; t < 4; t++) {
            int ci = tid + t * 256;
            int row = ci >> 3, ch = (ci & 7) * 8;
            CP_ASYNC16(sbase + (uint32_t)(row * LDH + ch) * 2u,
                       qbase + (size_t)row * QKVN + ch);
        }
        const uint32_t ks = sbase + (uint32_t)AK_OFF * 2u;
        const uint32_t vs = sbase + (uint32_t)AV_OFF * 2u;
        #pragma unroll
        for (int t = 0; t < 2; t++) {
            int ci = tid + t * 256;
            int row = ci >> 3, ch = (ci & 7) * 8;
            CP_ASYNC16(ks + (uint32_t)(row * LDH + ch) * 2u,
                       kbase + (size_t)row * QKVN + ch);
            CP_ASYNC16(vs + (uint32_t)(row * LDH + ch) * 2u,
                       vbase + (size_t)row * QKVN + ch);
        }
        CP_COMMIT();
    }
    if (ntiles > 1) issue_kv(1, 1);

    float o[8][4];
    #pragma unroll
    for (int nj = 0; nj < 8; nj++)
        #pragma unroll
        for (int t = 0; t < 4; t++) o[nj][t] = 0.f;
    float m0 = -1e30f, m1 = -1e30f, l0 = 0.f, l1 = 0.f;

    const int q0g = qt0 + wid * 16 + r;
    const int qmax_warp = qt0 + wid * 16 + 15;

    uint32_t qa[4][4];

    for (int kt = 0; kt < ntiles; kt++) {
        if (kt + 1 < ntiles) { CP_WAIT(1); } else { CP_WAIT(0); }
        __syncthreads();
        if (kt + 2 < ntiles) issue_kv(kt + 2, (kt + 2) % 3);

        if (kt == 0) {
            const uint32_t qaddr = sbase + (uint32_t)(((wid * 16 + l15) * LDH + lhi * 8) * 2);
            __half2 sc = __floats2half2_rn(0.18033688f, 0.18033688f);
            #pragma unroll
            for (int kk = 0; kk < 4; kk++) {
                LDMX4(qa[kk], qaddr + (uint32_t)(kk * 16 * 2));
                #pragma unroll
                for (int j = 0; j < 4; j++) {
                    __half2 v = *reinterpret_cast<__half2*>(&qa[kk][j]);
                    v = __hmul2(v, sc);
                    qa[kk][j] = *reinterpret_cast<uint32_t*>(&v);
                }
            }
        }

        if (kt * 64 <= qmax_warp) {
            const int buf = kt % 3;
            const uint32_t Kb = sbase + (uint32_t)(AK_OFF + buf * 64 * LDH) * 2u;
            const uint32_t Vb = sbase + (uint32_t)(AV_OFF + buf * 64 * LDH) * 2u;

            float s[8][4];
            #pragma unroll
            for (int nj = 0; nj < 8; nj++)
                #pragma unroll
                for (int t = 0; t < 4; t++) s[nj][t] = 0.f;

            const int g = lane >> 3;
            #pragma unroll
            for (int g2 = 0; g2 < 4; g2++) {
                const uint32_t rowb = Kb +
                    (uint32_t)(((16 * g2 + (g >> 1) * 8 + (lane & 7)) * LDH) * 2);
                #pragma unroll
                for (int kk = 0; kk < 4; kk++) {
                    uint32_t bk[4];
                    LDMX4(bk, rowb + (uint32_t)((kk * 16 + (g & 1) * 8) * 2));
                    mma_f16(s[2 * g2],     qa[kk], bk[0], bk[1]);
                    mma_f16(s[2 * g2 + 1], qa[kk], bk[2], bk[3]);
                }
            }

            if (kt * 64 + 63 > qt0 + wid * 16) {
                #pragma unroll
                for (int nj = 0; nj < 8; nj++) {
                    int k0c = kt * 64 + nj * 8 + c * 2;
                    if (k0c     > q0g)     s[nj][0] = -1e30f;
                    if (k0c + 1 > q0g)     s[nj][1] = -1e30f;
                    if (k0c     > q0g + 8) s[nj][2] = -1e30f;
                    if (k0c + 1 > q0g + 8) s[nj][3] = -1e30f;
                }
            }

            float mt0 = -1e30f, mt1 = -1e30f;
            #pragma unroll
            for (int nj = 0; nj < 8; nj++) {
                mt0 = fmaxf(mt0, fmaxf(s[nj][0], s[nj][1]));
                mt1 = fmaxf(mt1, fmaxf(s[nj][2], s[nj][3]));
            }
            mt0 = fmaxf(mt0, __shfl_xor_sync(0xffffffffu, mt0, 1));
            mt0 = fmaxf(mt0, __shfl_xor_sync(0xffffffffu, mt0, 2));
            mt1 = fmaxf(mt1, __shfl_xor_sync(0xffffffffu, mt1, 1));
            mt1 = fmaxf(mt1, __shfl_xor_sync(0xffffffffu, mt1, 2));

            float mn0 = fmaxf(m0, mt0), mn1 = fmaxf(m1, mt1);
            float cr0 = ex2f(m0 - mn0), cr1 = ex2f(m1 - mn1);
            float ls0 = 0.f, ls1 = 0.f;
            #pragma unroll
            for (int nj = 0; nj < 8; nj++) {
                s[nj][0] = ex2f(s[nj][0] - mn0);
                s[nj][1] = ex2f(s[nj][1] - mn0);
                s[nj][2] = ex2f(s[nj][2] - mn1);
                s[nj][3] = ex2f(s[nj][3] - mn1);
                ls0 += s[nj][0] + s[nj][1];
                ls1 += s[nj][2] + s[nj][3];
            }
            ls0 += __shfl_xor_sync(0xffffffffu, ls0, 1);
            ls0 += __shfl_xor_sync(0xffffffffu, ls0, 2);
            ls1 += __shfl_xor_sync(0xffffffffu, ls1, 1);
            ls1 += __shfl_xor_sync(0xffffffffu, ls1, 2);
            l0 = l0 * cr0 + ls0;
            l1 = l1 * cr1 + ls1;
            m0 = mn0; m1 = mn1;
            #pragma unroll
            for (int nj = 0; nj < 8; nj++) {
                o[nj][0] *= cr0; o[nj][1] *= cr0;
                o[nj][2] *= cr1; o[nj][3] *= cr1;
            }

            #pragma unroll
            for (int kk = 0; kk < 4; kk++) {
                uint32_t pa[4];
                pa[0] = pack_h2(s[2 * kk][0],     s[2 * kk][1]);
                pa[1] = pack_h2(s[2 * kk][2],     s[2 * kk][3]);
                pa[2] = pack_h2(s[2 * kk + 1][0], s[2 * kk + 1][1]);
                pa[3] = pack_h2(s[2 * kk + 1][2], s[2 * kk + 1][3]);
                const uint32_t rowb = Vb + (uint32_t)(((kk * 16 + l15) * LDH + lhi * 8) * 2);
                #pragma unroll
                for (int nj2 = 0; nj2 < 4; nj2++) {
                    uint32_t bv[4];
                    LDMX4T(bv, rowb + (uint32_t)((nj2 * 16) * 2));
                    mma_f16(o[2 * nj2],     pa, bv[0], bv[1]);
                    mma_f16(o[2 * nj2 + 1], pa, bv[2], bv[3]);
                }
            }
        }
    }

    float inv0 = 1.f / l0, inv1 = 1.f / l1;
    #pragma unroll
    for (int nj = 0; nj < 8; nj++) {
        int col = h * DH + nj * 8 + c * 2;
        size_t g0 = (size_t)(b * SEQ + q0g) * DM + col;
        size_t g1 = (size_t)(b * SEQ + q0g + 8) * DM + col;
        *(__half2*)(Z + g0) = __floats2half2_rn(o[nj][0] * inv0, o[nj][1] * inv0);
        *(__half2*)(Z + g1) = __floats2half2_rn(o[nj][2] * inv1, o[nj][3] * inv1);
    }
}

// ---------------- launch -----------------------------------------------------
extern "C" void kernel_launch(void* const* d_in, const int* in_sizes, int n_in,
                              void* d_out, int out_size) {
    const float* resid_pre = (const float*)d_in[0];
    const float* W_Q   = (const float*)d_in[1];
    const float* b_Q   = (const float*)d_in[2];
    const float* W_K   = (const float*)d_in[3];
    const float* b_K   = (const float*)d_in[4];
    const float* W_V   = (const float*)d_in[5];
    const float* b_V   = (const float*)d_in[6];
    const float* W_O   = (const float*)d_in[7];
    const float* b_O   = (const float*)d_in[8];
    const float* ln1_w = (const float*)d_in[9];
    const float* ln1_b = (const float*)d_in[10];
    const float* ln2_w = (const float*)d_in[11];
    const float* ln2_b = (const float*)d_in[12];
    const float* W_in  = (const float*)d_in[13];
    const float* b_in  = (const float*)d_in[14];
    const float* W_out = (const float*)d_in[15];
    const float* b_out = (const float*)d_in[16];
    float* out = (float*)d_out;

    float *pbqkv, *pmid;
    __half *px_h, *pwqkv_h, *pqkv_h, *pz_h, *py_h, *ph_h, *pwo_h, *pwin_h, *pwout_h;
    cudaGetSymbolAddress((void**)&px_h,    g_x_h);
    cudaGetSymbolAddress((void**)&pwqkv_h, g_wqkv_h);
    cudaGetSymbolAddress((void**)&pbqkv,   g_bqkv);
    cudaGetSymbolAddress((void**)&pqkv_h,  g_qkv_h);
    cudaGetSymbolAddress((void**)&pz_h,    g_z_h);
    cudaGetSymbolAddress((void**)&pmid,    g_mid);
    cudaGetSymbolAddress((void**)&py_h,    g_y_h);
    cudaGetSymbolAddress((void**)&ph_h,    g_h_h);
    cudaGetSymbolAddress((void**)&pwo_h,   g_wo_h);
    cudaGetSymbolAddress((void**)&pwin_h,  g_win_h);
    cudaGetSymbolAddress((void**)&pwout_h, g_wout_h);

    cudaFuncSetAttribute((const void*)gemm_h<0,8,3>, cudaFuncAttributeMaxDynamicSharedMemorySize, (GemmHCfg<8,3>::SMEM));
    cudaFuncSetAttribute((const void*)gemm_h<1,8,3>, cudaFuncAttributeMaxDynamicSharedMemorySize, (GemmHCfg<8,3>::SMEM));
    cudaFuncSetAttribute((const void*)gemm_h<2,4,4>, cudaFuncAttributeMaxDynamicSharedMemorySize, (GemmHCfg<4,4>::SMEM));
    cudaFuncSetAttribute((const void*)attn_h,        cudaFuncAttributeMaxDynamicSharedMemorySize, ATTNH_SMEM);

    prep_weights<<<(DM * DM + 255) / 256, 256>>>(
        W_Q, W_K, W_V, W_O, W_in, W_out, b_Q, b_K, b_V,
        pwqkv_h, pwo_h, pwin_h, pwout_h, pbqkv);

    ln4_h<<<ROWS / 4, 256>>>(resid_pre, ln1_w, ln1_b, px_h);
    gemm_h<0,8,3><<<dim3(QKVN / 128, ROWS / 128), 256, (GemmHCfg<8,3>::SMEM)>>>(
        px_h, pwqkv_h, pbqkv, nullptr, pqkv_h, ROWS, QKVN, DM);
    attn_h<<<dim3(SEQ / 128, NH, BATCH), 256, ATTNH_SMEM>>>(pqkv_h, pz_h);
    // O-proj: BN=64, 4-stage pipeline
    gemm_h<2,4,4><<<dim3(DM / 64, ROWS / 128), 256, (GemmHCfg<4,4>::SMEM)>>>(
        pz_h, pwo_h, b_O, resid_pre, pmid, ROWS, DM, DM);
    ln4_h<<<ROWS / 4, 256>>>(pmid, ln2_w, ln2_b, py_h);
    gemm_h<1,8,3><<<dim3(DMLP / 128, ROWS / 128), 256, (GemmHCfg<8,3>::SMEM)>>>(
        py_h, pwin_h, b_in, nullptr, ph_h, ROWS, DMLP, DM);
    // MLP-out: BN=64, 4-stage pipeline
    gemm_h<2,4,4><<<dim3(DM / 64, ROWS / 128), 256, (GemmHCfg<4,4>::SMEM)>>>(
        ph_h, pwout_h, b_out, pmid, out, ROWS, DM, DMLP);
}

// round 16
// speedup vs baseline: 1.0320x; 1.0172x over previous
#include <cuda_runtime.h>
#include <cuda_fp16.h>
#include <cstdint>
#include <math.h>

#define DM    768
#define DMLP  3072
#define NH    12
#define DH    64
#define BATCH 2
#define SEQ   2048
#define ROWS  (BATCH*SEQ)     /* 4096 */
#define QKVN  (3*DM)          /* 2304 */

// ---------------- scratch (static device globals; no allocation) -----------
__device__ __align__(16) __half g_x_h   [ROWS*DM];     // ln1 output
__device__ __align__(16) __half g_wqkv_h[DM*QKVN];     // packed QKV W [K,N]
__device__ float g_bqkv [QKVN];
__device__ __align__(16) __half g_qkv_h [ROWS*QKVN];   // Q|K|V per token
__device__ __align__(16) __half g_z_h   [ROWS*DM];     // attention output
__device__ float g_mid  [ROWS*DM];                     // resid_mid (fp32)
__device__ __align__(16) __half g_y_h   [ROWS*DM];     // ln2 output
__device__ __align__(16) __half g_h_h   [ROWS*DMLP];   // MLP hidden
__device__ __align__(16) __half g_wo_h  [DM*DM];       // W_O   fp16 [K,N]
__device__ __align__(16) __half g_win_h [DM*DMLP];     // W_in  fp16 [K,N]
__device__ __align__(16) __half g_wout_h[DMLP*DM];     // W_out fp16 [K,N]

// ======================= helpers ============================================
__device__ __forceinline__ uint32_t smem_u32(const void* p) {
    uint32_t a;
    asm("{ .reg .u64 t; cvta.to.shared.u64 t, %1; cvt.u32.u64 %0, t; }"
        : "=r"(a) : "l"(p));
    return a;
}
__device__ __forceinline__ float gelu_new(float v) {
    float v3 = v * v * v;
    return 0.5f * v * (1.f + tanhf(0.7978845608028654f * (v + 0.044715f * v3)));
}
__device__ __forceinline__ uint32_t pack_h2(float a, float b) {
    __half2 h = __floats2half2_rn(a, b);
    return *reinterpret_cast<uint32_t*>(&h);
}
__device__ __forceinline__ float ex2f(float x) {
    float y;
    asm("ex2.approx.f32 %0, %1;" : "=f"(y) : "f"(x));
    return y;
}
#define CP_ASYNC16(sa, gp) \
    asm volatile("cp.async.cg.shared.global [%0], [%1], 16;" :: "r"(sa), "l"(gp))
#define CP_COMMIT() asm volatile("cp.async.commit_group;" ::: "memory")
#define CP_WAIT(n)  asm volatile("cp.async.wait_group %0;" :: "n"(n) : "memory")

#define LDMX4(r, addr) \
    asm volatile("ldmatrix.sync.aligned.m8n8.x4.shared.b16 {%0,%1,%2,%3}, [%4];" \
        : "=r"((r)[0]), "=r"((r)[1]), "=r"((r)[2]), "=r"((r)[3]) : "r"(addr))
#define LDMX4T(r, addr) \
    asm volatile("ldmatrix.sync.aligned.m8n8.x4.trans.shared.b16 {%0,%1,%2,%3}, [%4];" \
        : "=r"((r)[0]), "=r"((r)[1]), "=r"((r)[2]), "=r"((r)[3]) : "r"(addr))

__device__ __forceinline__ void mma_f16(float* c, const uint32_t* a,
                                        uint32_t b0, uint32_t b1) {
    asm volatile(
        "mma.sync.aligned.m16n8k16.row.col.f32.f16.f16.f32 "
        "{%0,%1,%2,%3}, {%4,%5,%6,%7}, {%8,%9}, {%0,%1,%2,%3};\n"
        : "+f"(c[0]), "+f"(c[1]), "+f"(c[2]), "+f"(c[3])
        : "r"(a[0]), "r"(a[1]), "r"(a[2]), "r"(a[3]), "r"(b0), "r"(b1));
}

// ====== fp16 mma.sync GEMM (ldmatrix, BK=64): C[M,N] = A[M,K] @ B[K,N] ======
#define LDAH2 72
#define AH_STAGE2 (128*LDAH2)

template<int NJ> struct GemmHCfg {
    static const int BN      = NJ * 16;
    static const int LDBH_   = BN + 8;
    static const int B_STAGE = 64 * LDBH_;
    static const int STAGE   = AH_STAGE2 + B_STAGE;
    static const int SMEM    = 3 * STAGE * 2;
    static const int TBH     = BN / 32;
};

// EPI: 0 = bias->half, 1 = bias+gelu->half, 2 = bias+residual->float
template<int EPI, int NJ>
__global__ __launch_bounds__(256, 2)
void gemm_h(const __half* __restrict__ A, const __half* __restrict__ B,
            const float* __restrict__ bias, const float* __restrict__ R,
            void* __restrict__ Cout, int M, int N, int K) {
    typedef GemmHCfg<NJ> CFG;
    extern __shared__ __half smh[];
    const uint32_t sbase = smem_u32(smh);
    const int tid = threadIdx.x, lane = tid & 31, wid = tid >> 5;
    const int wm = wid & 3, wn = wid >> 2;
    const int bm = blockIdx.y * 128, bn = blockIdx.x * CFG::BN;
    const int niter = K >> 6;

    int ar[4], ac[4];
    #pragma unroll
    for (int t = 0; t < 4; t++) {
        int ci = tid + t * 256;
        ar[t] = ci >> 3;  ac[t] = (ci & 7) * 8;
    }
    int br[CFG::TBH], bc[CFG::TBH];
    #pragma unroll
    for (int t = 0; t < CFG::TBH; t++) {
        int ci = tid + t * 256;
        br[t] = ci / (CFG::BN / 8);
        bc[t] = (ci % (CFG::BN / 8)) * 8;
    }

    float acc[2][NJ][4];
    #pragma unroll
    for (int mi = 0; mi < 2; mi++)
        #pragma unroll
        for (int nj = 0; nj < NJ; nj++)
            #pragma unroll
            for (int r = 0; r < 4; r++) acc[mi][nj][r] = 0.f;

    auto issue = [&](int ks, int buf) {
        const int k0 = ks << 6;
        const uint32_t s0 = sbase + (uint32_t)buf * CFG::STAGE * 2u;
        #pragma unroll
        for (int t = 0; t < 4; t++)
            CP_ASYNC16(s0 + (uint32_t)(ar[t] * LDAH2 + ac[t]) * 2u,
                       A + (size_t)(bm + ar[t]) * K + k0 + ac[t]);
        const uint32_t s1 = s0 + AH_STAGE2 * 2u;
        #pragma unroll
        for (int t = 0; t < CFG::TBH; t++)
            CP_ASYNC16(s1 + (uint32_t)(br[t] * CFG::LDBH_ + bc[t]) * 2u,
                       B + (size_t)(k0 + br[t]) * N + bn + bc[t]);
        CP_COMMIT();
    };

    issue(0, 0);
    issue(1, 1);

    const int l15 = lane & 15, lhi = lane >> 4;
    const uint32_t aAddrBase = (uint32_t)(((wm * 32 + l15) * LDAH2 + lhi * 8) * 2);
    const uint32_t bAddrBase = (uint32_t)((l15 * CFG::LDBH_ + wn * (NJ * 8) + lhi * 8) * 2);

    for (int i = 0; i < niter; i++) {
        if (i + 1 < niter) { CP_WAIT(1); } else { CP_WAIT(0); }
        __syncthreads();
        if (i + 2 < niter) issue(i + 2, (i + 2) % 3);

        const uint32_t sA = sbase + (uint32_t)((i % 3) * CFG::STAGE) * 2u;
        const uint32_t sB = sA + AH_STAGE2 * 2u;

        #pragma unroll
        for (int kk = 0; kk < 4; kk++) {
            uint32_t a[2][4];
            #pragma unroll
            for (int mi = 0; mi < 2; mi++)
                LDMX4(a[mi], sA + aAddrBase + (uint32_t)((mi * 16 * LDAH2 + kk * 16) * 2));
            #pragma unroll
            for (int nj2 = 0; nj2 < NJ / 2; nj2++) {
                uint32_t bf[4];
                LDMX4T(bf, sB + bAddrBase + (uint32_t)((kk * 16 * CFG::LDBH_ + nj2 * 16) * 2));
                #pragma unroll
                for (int hh = 0; hh < 2; hh++) {
                    #pragma unroll
                    for (int mi = 0; mi < 2; mi++)
                        mma_f16(acc[mi][nj2 * 2 + hh], a[mi], bf[hh * 2], bf[hh * 2 + 1]);
                }
            }
        }
    }

    #pragma unroll
    for (int mi = 0; mi < 2; mi++) {
        const int row0 = bm + wm * 32 + mi * 16 + (lane >> 2);
        #pragma unroll
        for (int nj = 0; nj < NJ; nj++) {
            const int col0 = bn + wn * (NJ * 8) + nj * 8 + (lane & 3) * 2;
            const float b0 = bias[col0], b1 = bias[col0 + 1];
            #pragma unroll
            for (int hh = 0; hh < 2; hh++) {
                const int row = row0 + hh * 8;
                float v0 = acc[mi][nj][hh * 2 + 0] + b0;
                float v1 = acc[mi][nj][hh * 2 + 1] + b1;
                size_t g = (size_t)row * N + col0;
                if (EPI == 0) {
                    *(__half2*)((__half*)Cout + g) = __floats2half2_rn(v0, v1);
                } else if (EPI == 1) {
                    *(__half2*)((__half*)Cout + g) =
                        __floats2half2_rn(gelu_new(v0), gelu_new(v1));
                } else {
                    float2 rv = *(const float2*)(R + g);
                    float2 o; o.x = v0 + rv.x; o.y = v1 + rv.y;
                    *(float2*)((float*)Cout + g) = o;
                }
            }
        }
    }
}

// ---------------- layernorm: 4 rows/block, 64 thr/row, float4, 1 pass -------
__global__ __launch_bounds__(256)
void ln4_h(const float* __restrict__ in, const float* __restrict__ w,
           const float* __restrict__ b, __half* __restrict__ out) {
    const int tid = threadIdx.x;
    const int rloc = tid >> 6;
    const int t    = tid & 63;
    const int row  = blockIdx.x * 4 + rloc;
    const int lane = tid & 31;
    const int wIdx = (tid >> 5) & 1;

    const float4* xp = (const float4*)(in + (size_t)row * DM);
    float4 v[3];
    float s = 0.f, ss = 0.f;
    #pragma unroll
    for (int k = 0; k < 3; k++) {
        v[k] = xp[t + k * 64];
        s  += v[k].x + v[k].y + v[k].z + v[k].w;
        ss += v[k].x * v[k].x + v[k].y * v[k].y + v[k].z * v[k].z + v[k].w * v[k].w;
    }
    #pragma unroll
    for (int o = 16; o; o >>= 1) {
        s  += __shfl_xor_sync(0xffffffffu, s,  o);
        ss += __shfl_xor_sync(0xffffffffu, ss, o);
    }
    __shared__ float sb[4][2], qb[4][2];
    if (lane == 0) { sb[rloc][wIdx] = s; qb[rloc][wIdx] = ss; }
    __syncthreads();
    s  = sb[rloc][0] + sb[rloc][1];
    ss = qb[rloc][0] + qb[rloc][1];
    float mean = s * (1.f / DM);
    float inv  = rsqrtf(ss * (1.f / DM) - mean * mean + 1e-5f);

    const float4* wp = (const float4*)w;
    const float4* bp = (const float4*)b;
    __half2* op = (__half2*)(out + (size_t)row * DM);
    #pragma unroll
    for (int k = 0; k < 3; k++) {
        float4 wv = wp[t + k * 64], bv = bp[t + k * 64];
        float o0 = (v[k].x - mean) * inv * wv.x + bv.x;
        float o1 = (v[k].y - mean) * inv * wv.y + bv.y;
        float o2 = (v[k].z - mean) * inv * wv.z + bv.z;
        float o3 = (v[k].w - mean) * inv * wv.w + bv.w;
        op[(t + k * 64) * 2]     = __floats2half2_rn(o0, o1);
        op[(t + k * 64) * 2 + 1] = __floats2half2_rn(o2, o3);
    }
}

// ---------------- merged weight prep (vectorized) ----------------------------
__global__ void prep_weights(const float* __restrict__ WQ, const float* __restrict__ WK,
                             const float* __restrict__ WV, const float* __restrict__ WO,
                             const float* __restrict__ Win, const float* __restrict__ Wout,
                             const float* __restrict__ bQ, const float* __restrict__ bK,
                             const float* __restrict__ bV,
                             __half* __restrict__ Wqkv, __half* __restrict__ Wo_h,
                             __half* __restrict__ Win_h, __half* __restrict__ Wout_h,
                             float* __restrict__ bias) {
    int idx = blockIdx.x * 256 + threadIdx.x;
    if (idx < DM * DM) {
        float4 wi = ((const float4*)Win)[idx];
        float4 wo = ((const float4*)Wout)[idx];
        ((__half2*)Win_h)[idx * 2]      = __floats2half2_rn(wi.x, wi.y);
        ((__half2*)Win_h)[idx * 2 + 1]  = __floats2half2_rn(wi.z, wi.w);
        ((__half2*)Wout_h)[idx * 2]     = __floats2half2_rn(wo.x, wo.y);
        ((__half2*)Wout_h)[idx * 2 + 1] = __floats2half2_rn(wo.z, wo.w);
        Wo_h[idx] = __float2half_rn(WO[idx]);
        int k = idx / DM, n = idx % DM;
        int h = n >> 6, e = n & 63;
        int src = h * (DM * DH) + k * DH + e;
        Wqkv[(size_t)k * QKVN + n]          = __float2half_rn(WQ[src]);
        Wqkv[(size_t)k * QKVN + DM + n]     = __float2half_rn(WK[src]);
        Wqkv[(size_t)k * QKVN + 2 * DM + n] = __float2half_rn(WV[src]);
    }
    if (idx < DM) {
        bias[idx]          = bQ[idx];
        bias[DM + idx]     = bK[idx];
        bias[2 * DM + idx] = bV[idx];
    }
}

// ============== flash attention via fp16 mma.sync (causal, cp.async) ========
// 128 thr / 4 warps; Q tile 64 rows (16/warp); K/V tile 64 keys, 3-buffer ring;
// 1 sync per K-tile; log2-domain softmax. 3 CTAs/SM (63 KB smem).
#define LDH 72
#define AK_OFF (64*LDH)
#define AV_OFF (AK_OFF + 3*64*LDH)
#define ATTNH_SMEM ((AV_OFF + 3*64*LDH)*2)   /* 448*72*2 = 64512 B */

__global__ __launch_bounds__(128, 3)
void attn_h(const __half* __restrict__ QKV, __half* __restrict__ Z) {
    extern __shared__ __half smh[];
    const uint32_t sbase = smem_u32(smh);

    const int tid = threadIdx.x, lane = tid & 31, wid = tid >> 5;
    const int r = lane >> 2, c = lane & 3;
    const int l15 = lane & 15, lhi = lane >> 4;
    const int qt = gridDim.x - 1 - blockIdx.x;       // heavy blocks first
    const int qt0 = qt * 64;
    const int h = blockIdx.y, b = blockIdx.z;

    const __half* qbase = QKV + ((size_t)(b * SEQ + qt0)) * QKVN + h * DH;
    const __half* kbase = QKV + ((size_t)b * SEQ) * QKVN + DM     + h * DH;
    const __half* vbase = QKV + ((size_t)b * SEQ) * QKVN + 2 * DM + h * DH;

    const int ntiles = qt0 / 64 + 1;

    auto issue_kv = [&](int kt, int buf) {
        const __half* kb = kbase + (size_t)(kt * 64) * QKVN;
        const __half* vb = vbase + (size_t)(kt * 64) * QKVN;
        const uint32_t ks = sbase + (uint32_t)(AK_OFF + buf * 64 * LDH) * 2u;
        const uint32_t vs = sbase + (uint32_t)(AV_OFF + buf * 64 * LDH) * 2u;
        #pragma unroll
        for (int t = 0; t < 4; t++) {
            int ci = tid + t * 128;                 // 0..511
            int row = ci >> 3, ch = (ci & 7) * 8;
            CP_ASYNC16(ks + (uint32_t)(row * LDH + ch) * 2u,
                       kb + (size_t)row * QKVN + ch);
            CP_ASYNC16(vs + (uint32_t)(row * LDH + ch) * 2u,
                       vb + (size_t)row * QKVN + ch);
        }
        CP_COMMIT();
    };

    {   // group 0: Q (64 rows) + KV tile 0
        #pragma unroll
        for (int t = 0; t < 4; t++) {
            int ci = tid + t * 128;                 // 0..511
            int row = ci >> 3, ch = (ci & 7) * 8;
            CP_ASYNC16(sbase + (uint32_t)(row * LDH + ch) * 2u,
                       qbase + (size_t)row * QKVN + ch);
        }
        const uint32_t ks = sbase + (uint32_t)AK_OFF * 2u;
        const uint32_t vs = sbase + (uint32_t)AV_OFF * 2u;
        #pragma unroll
        for (int t = 0; t < 4; t++) {
            int ci = tid + t * 128;
            int row = ci >> 3, ch = (ci & 7) * 8;
            CP_ASYNC16(ks + (uint32_t)(row * LDH + ch) * 2u,
                       kbase + (size_t)row * QKVN + ch);
            CP_ASYNC16(vs + (uint32_t)(row * LDH + ch) * 2u,
                       vbase + (size_t)row * QKVN + ch);
        }
        CP_COMMIT();
    }
    if (ntiles > 1) issue_kv(1, 1);

    float o[8][4];
    #pragma unroll
    for (int nj = 0; nj < 8; nj++)
        #pragma unroll
        for (int t = 0; t < 4; t++) o[nj][t] = 0.f;
    float m0 = -1e30f, m1 = -1e30f, l0 = 0.f, l1 = 0.f;

    const int q0g = qt0 + wid * 16 + r;
    const int qmax_warp = qt0 + wid * 16 + 15;

    uint32_t qa[4][4];

    for (int kt = 0; kt < ntiles; kt++) {
        if (kt + 1 < ntiles) { CP_WAIT(1); } else { CP_WAIT(0); }
        __syncthreads();
        if (kt + 2 < ntiles) issue_kv(kt + 2, (kt + 2) % 3);

        if (kt == 0) {
            const uint32_t qaddr = sbase + (uint32_t)(((wid * 16 + l15) * LDH + lhi * 8) * 2);
            __half2 sc = __floats2half2_rn(0.18033688f, 0.18033688f);
            #pragma unroll
            for (int kk = 0; kk < 4; kk++) {
                LDMX4(qa[kk], qaddr + (uint32_t)(kk * 16 * 2));
                #pragma unroll
                for (int j = 0; j < 4; j++) {
                    __half2 v = *reinterpret_cast<__half2*>(&qa[kk][j]);
                    v = __hmul2(v, sc);
                    qa[kk][j] = *reinterpret_cast<uint32_t*>(&v);
                }
            }
        }

        if (kt * 64 <= qmax_warp) {
            const int buf = kt % 3;
            const uint32_t Kb = sbase + (uint32_t)(AK_OFF + buf * 64 * LDH) * 2u;
            const uint32_t Vb = sbase + (uint32_t)(AV_OFF + buf * 64 * LDH) * 2u;

            float s[8][4];
            #pragma unroll
            for (int nj = 0; nj < 8; nj++)
                #pragma unroll
                for (int t = 0; t < 4; t++) s[nj][t] = 0.f;

            const int g = lane >> 3;
            #pragma unroll
            for (int g2 = 0; g2 < 4; g2++) {
                const uint32_t rowb = Kb +
                    (uint32_t)(((16 * g2 + (g >> 1) * 8 + (lane & 7)) * LDH) * 2);
                #pragma unroll
                for (int kk = 0; kk < 4; kk++) {
                    uint32_t bk[4];
                    LDMX4(bk, rowb + (uint32_t)((kk * 16 + (g & 1) * 8) * 2));
                    mma_f16(s[2 * g2],     qa[kk], bk[0], bk[1]);
                    mma_f16(s[2 * g2 + 1], qa[kk], bk[2], bk[3]);
                }
            }

            if (kt * 64 + 63 > qt0 + wid * 16) {
                #pragma unroll
                for (int nj = 0; nj < 8; nj++) {
                    int k0c = kt * 64 + nj * 8 + c * 2;
                    if (k0c     > q0g)     s[nj][0] = -1e30f;
                    if (k0c + 1 > q0g)     s[nj][1] = -1e30f;
                    if (k0c     > q0g + 8) s[nj][2] = -1e30f;
                    if (k0c + 1 > q0g + 8) s[nj][3] = -1e30f;
                }
            }

            float mt0 = -1e30f, mt1 = -1e30f;
            #pragma unroll
            for (int nj = 0; nj < 8; nj++) {
                mt0 = fmaxf(mt0, fmaxf(s[nj][0], s[nj][1]));
                mt1 = fmaxf(mt1, fmaxf(s[nj][2], s[nj][3]));
            }
            mt0 = fmaxf(mt0, __shfl_xor_sync(0xffffffffu, mt0, 1));
            mt0 = fmaxf(mt0, __shfl_xor_sync(0xffffffffu, mt0, 2));
            mt1 = fmaxf(mt1, __shfl_xor_sync(0xffffffffu, mt1, 1));
            mt1 = fmaxf(mt1, __shfl_xor_sync(0xffffffffu, mt1, 2));

            float mn0 = fmaxf(m0, mt0), mn1 = fmaxf(m1, mt1);
            float cr0 = ex2f(m0 - mn0), cr1 = ex2f(m1 - mn1);
            float ls0 = 0.f, ls1 = 0.f;
            #pragma unroll
            for (int nj = 0; nj < 8; nj++) {
                s[nj][0] = ex2f(s[nj][0] - mn0);
                s[nj][1] = ex2f(s[nj][1] - mn0);
                s[nj][2] = ex2f(s[nj][2] - mn1);
                s[nj][3] = ex2f(s[nj][3] - mn1);
                ls0 += s[nj][0] + s[nj][1];
                ls1 += s[nj][2] + s[nj][3];
            }
            ls0 += __shfl_xor_sync(0xffffffffu, ls0, 1);
            ls0 += __shfl_xor_sync(0xffffffffu, ls0, 2);
            ls1 += __shfl_xor_sync(0xffffffffu, ls1, 1);
            ls1 += __shfl_xor_sync(0xffffffffu, ls1, 2);
            l0 = l0 * cr0 + ls0;
            l1 = l1 * cr1 + ls1;
            m0 = mn0; m1 = mn1;
            #pragma unroll
            for (int nj = 0; nj < 8; nj++) {
                o[nj][0] *= cr0; o[nj][1] *= cr0;
                o[nj][2] *= cr1; o[nj][3] *= cr1;
            }

            #pragma unroll
            for (int kk = 0; kk < 4; kk++) {
                uint32_t pa[4];
                pa[0] = pack_h2(s[2 * kk][0],     s[2 * kk][1]);
                pa[1] = pack_h2(s[2 * kk][2],     s[2 * kk][3]);
                pa[2] = pack_h2(s[2 * kk + 1][0], s[2 * kk + 1][1]);
                pa[3] = pack_h2(s[2 * kk + 1][2], s[2 * kk + 1][3]);
                const uint32_t rowb = Vb + (uint32_t)(((kk * 16 + l15) * LDH + lhi * 8) * 2);
                #pragma unroll
                for (int nj2 = 0; nj2 < 4; nj2++) {
                    uint32_t bv[4];
                    LDMX4T(bv, rowb + (uint32_t)((nj2 * 16) * 2));
                    mma_f16(o[2 * nj2],     pa, bv[0], bv[1]);
                    mma_f16(o[2 * nj2 + 1], pa, bv[2], bv[3]);
                }
            }
        }
    }

    float inv0 = 1.f / l0, inv1 = 1.f / l1;
    #pragma unroll
    for (int nj = 0; nj < 8; nj++) {
        int col = h * DH + nj * 8 + c * 2;
        size_t g0 = (size_t)(b * SEQ + q0g) * DM + col;
        size_t g1 = (size_t)(b * SEQ + q0g + 8) * DM + col;
        *(__half2*)(Z + g0) = __floats2half2_rn(o[nj][0] * inv0, o[nj][1] * inv0);
        *(__half2*)(Z + g1) = __floats2half2_rn(o[nj][2] * inv1, o[nj][3] * inv1);
    }
}

// ---------------- launch -----------------------------------------------------
extern "C" void kernel_launch(void* const* d_in, const int* in_sizes, int n_in,
                              void* d_out, int out_size) {
    const float* resid_pre = (const float*)d_in[0];
    const float* W_Q   = (const float*)d_in[1];
    const float* b_Q   = (const float*)d_in[2];
    const float* W_K   = (const float*)d_in[3];
    const float* b_K   = (const float*)d_in[4];
    const float* W_V   = (const float*)d_in[5];
    const float* b_V   = (const float*)d_in[6];
    const float* W_O   = (const float*)d_in[7];
    const float* b_O   = (const float*)d_in[8];
    const float* ln1_w = (const float*)d_in[9];
    const float* ln1_b = (const float*)d_in[10];
    const float* ln2_w = (const float*)d_in[11];
    const float* ln2_b = (const float*)d_in[12];
    const float* W_in  = (const float*)d_in[13];
    const float* b_in  = (const float*)d_in[14];
    const float* W_out = (const float*)d_in[15];
    const float* b_out = (const float*)d_in[16];
    float* out = (float*)d_out;

    float *pbqkv, *pmid;
    __half *px_h, *pwqkv_h, *pqkv_h, *pz_h, *py_h, *ph_h, *pwo_h, *pwin_h, *pwout_h;
    cudaGetSymbolAddress((void**)&px_h,    g_x_h);
    cudaGetSymbolAddress((void**)&pwqkv_h, g_wqkv_h);
    cudaGetSymbolAddress((void**)&pbqkv,   g_bqkv);
    cudaGetSymbolAddress((void**)&pqkv_h,  g_qkv_h);
    cudaGetSymbolAddress((void**)&pz_h,    g_z_h);
    cudaGetSymbolAddress((void**)&pmid,    g_mid);
    cudaGetSymbolAddress((void**)&py_h,    g_y_h);
    cudaGetSymbolAddress((void**)&ph_h,    g_h_h);
    cudaGetSymbolAddress((void**)&pwo_h,   g_wo_h);
    cudaGetSymbolAddress((void**)&pwin_h,  g_win_h);
    cudaGetSymbolAddress((void**)&pwout_h, g_wout_h);

    cudaFuncSetAttribute((const void*)gemm_h<0,8>, cudaFuncAttributeMaxDynamicSharedMemorySize, GemmHCfg<8>::SMEM);
    cudaFuncSetAttribute((const void*)gemm_h<1,8>, cudaFuncAttributeMaxDynamicSharedMemorySize, GemmHCfg<8>::SMEM);
    cudaFuncSetAttribute((const void*)gemm_h<2,4>, cudaFuncAttributeMaxDynamicSharedMemorySize, GemmHCfg<4>::SMEM);
    cudaFuncSetAttribute((const void*)attn_h,      cudaFuncAttributeMaxDynamicSharedMemorySize, ATTNH_SMEM);

    prep_weights<<<(DM * DM + 255) / 256, 256>>>(
        W_Q, W_K, W_V, W_O, W_in, W_out, b_Q, b_K, b_V,
        pwqkv_h, pwo_h, pwin_h, pwout_h, pbqkv);

    ln4_h<<<ROWS / 4, 256>>>(resid_pre, ln1_w, ln1_b, px_h);
    gemm_h<0,8><<<dim3(QKVN / 128, ROWS / 128), 256, GemmHCfg<8>::SMEM>>>(
        px_h, pwqkv_h, pbqkv, nullptr, pqkv_h, ROWS, QKVN, DM);
    attn_h<<<dim3(SEQ / 64, NH, BATCH), 128, ATTNH_SMEM>>>(pqkv_h, pz_h);
    gemm_h<2,4><<<dim3(DM / 64, ROWS / 128), 256, GemmHCfg<4>::SMEM>>>(
        pz_h, pwo_h, b_O, resid_pre, pmid, ROWS, DM, DM);
    ln4_h<<<ROWS / 4, 256>>>(pmid, ln2_w, ln2_b, py_h);
    gemm_h<1,8><<<dim3(DMLP / 128, ROWS / 128), 256, GemmHCfg<8>::SMEM>>>(
        py_h, pwin_h, b_in, nullptr, ph_h, ROWS, DMLP, DM);
    gemm_h<2,4><<<dim3(DM / 64, ROWS / 128), 256, GemmHCfg<4>::SMEM>>>(
        ph_h, pwout_h, b_out, pmid, out, ROWS, DM, DMLP);
}

// round 17
// speedup vs baseline: 1.0342x; 1.0021x over previous
#include <cuda_runtime.h>
#include <cuda_fp16.h>
#include <cstdint>
#include <math.h>

#define DM    768
#define DMLP  3072
#define NH    12
#define DH    64
#define BATCH 2
#define SEQ   2048
#define ROWS  (BATCH*SEQ)     /* 4096 */
#define QKVN  (3*DM)          /* 2304 */

// ---------------- scratch (static device globals; no allocation) -----------
__device__ __align__(16) __half g_x_h   [ROWS*DM];     // ln1 output
__device__ __align__(16) __half g_wqkv_h[DM*QKVN];     // packed QKV W [K,N]
__device__ float g_bqkv [QKVN];
__device__ __align__(16) __half g_qkv_h [ROWS*QKVN];   // Q|K|V per token
__device__ __align__(16) __half g_z_h   [ROWS*DM];     // attention output
__device__ float g_mid  [ROWS*DM];                     // resid_mid (fp32)
__device__ __align__(16) __half g_y_h   [ROWS*DM];     // ln2 output
__device__ __align__(16) __half g_h_h   [ROWS*DMLP];   // MLP hidden
__device__ __align__(16) __half g_wo_h  [DM*DM];       // W_O   fp16 [K,N]
__device__ __align__(16) __half g_win_h [DM*DMLP];     // W_in  fp16 [K,N]
__device__ __align__(16) __half g_wout_h[DMLP*DM];     // W_out fp16 [K,N]

// ======================= helpers ============================================
__device__ __forceinline__ uint32_t smem_u32(const void* p) {
    uint32_t a;
    asm("{ .reg .u64 t; cvta.to.shared.u64 t, %1; cvt.u32.u64 %0, t; }"
        : "=r"(a) : "l"(p));
    return a;
}
__device__ __forceinline__ float gelu_new(float v) {
    float v3 = v * v * v;
    return 0.5f * v * (1.f + tanhf(0.7978845608028654f * (v + 0.044715f * v3)));
}
__device__ __forceinline__ uint32_t pack_h2(float a, float b) {
    __half2 h = __floats2half2_rn(a, b);
    return *reinterpret_cast<uint32_t*>(&h);
}
__device__ __forceinline__ float ex2f(float x) {
    float y;
    asm("ex2.approx.f32 %0, %1;" : "=f"(y) : "f"(x));
    return y;
}
#define CP_ASYNC16(sa, gp) \
    asm volatile("cp.async.cg.shared.global [%0], [%1], 16;" :: "r"(sa), "l"(gp))
#define CP_COMMIT() asm volatile("cp.async.commit_group;" ::: "memory")
#define CP_WAIT(n)  asm volatile("cp.async.wait_group %0;" :: "n"(n) : "memory")

#define LDMX4(r, addr) \
    asm volatile("ldmatrix.sync.aligned.m8n8.x4.shared.b16 {%0,%1,%2,%3}, [%4];" \
        : "=r"((r)[0]), "=r"((r)[1]), "=r"((r)[2]), "=r"((r)[3]) : "r"(addr))
#define LDMX4T(r, addr) \
    asm volatile("ldmatrix.sync.aligned.m8n8.x4.trans.shared.b16 {%0,%1,%2,%3}, [%4];" \
        : "=r"((r)[0]), "=r"((r)[1]), "=r"((r)[2]), "=r"((r)[3]) : "r"(addr))

__device__ __forceinline__ void mma_f16(float* c, const uint32_t* a,
                                        uint32_t b0, uint32_t b1) {
    asm volatile(
        "mma.sync.aligned.m16n8k16.row.col.f32.f16.f16.f32 "
        "{%0,%1,%2,%3}, {%4,%5,%6,%7}, {%8,%9}, {%0,%1,%2,%3};\n"
        : "+f"(c[0]), "+f"(c[1]), "+f"(c[2]), "+f"(c[3])
        : "r"(a[0]), "r"(a[1]), "r"(a[2]), "r"(a[3]), "r"(b0), "r"(b1));
}

// ====== fp16 mma.sync GEMM (ldmatrix, BK=64): C[M,N] = A[M,K] @ B[K,N] ======
#define LDAH2 72
#define AH_STAGE2 (128*LDAH2)

template<int NJ> struct GemmHCfg {
    static const int BN      = NJ * 16;
    static const int LDBH_   = BN + 8;
    static const int B_STAGE = 64 * LDBH_;
    static const int STAGE   = AH_STAGE2 + B_STAGE;
    static const int SMEM    = 3 * STAGE * 2;
    static const int TBH     = BN / 32;
};

// EPI: 0 = bias->half, 1 = bias+gelu->half, 2 = bias+residual->float
template<int EPI, int NJ>
__global__ __launch_bounds__(256, 2)
void gemm_h(const __half* __restrict__ A, const __half* __restrict__ B,
            const float* __restrict__ bias, const float* __restrict__ R,
            void* __restrict__ Cout, int M, int N, int K) {
    typedef GemmHCfg<NJ> CFG;
    extern __shared__ __half smh[];
    const uint32_t sbase = smem_u32(smh);
    const int tid = threadIdx.x, lane = tid & 31, wid = tid >> 5;
    const int wm = wid & 3, wn = wid >> 2;
    const int bm = blockIdx.y * 128, bn = blockIdx.x * CFG::BN;
    const int niter = K >> 6;

    int ar[4], ac[4];
    #pragma unroll
    for (int t = 0; t < 4; t++) {
        int ci = tid + t * 256;
        ar[t] = ci >> 3;  ac[t] = (ci & 7) * 8;
    }
    int br[CFG::TBH], bc[CFG::TBH];
    #pragma unroll
    for (int t = 0; t < CFG::TBH; t++) {
        int ci = tid + t * 256;
        br[t] = ci / (CFG::BN / 8);
        bc[t] = (ci % (CFG::BN / 8)) * 8;
    }

    float acc[2][NJ][4];
    #pragma unroll
    for (int mi = 0; mi < 2; mi++)
        #pragma unroll
        for (int nj = 0; nj < NJ; nj++)
            #pragma unroll
            for (int r = 0; r < 4; r++) acc[mi][nj][r] = 0.f;

    auto issue = [&](int ks, int buf) {
        const int k0 = ks << 6;
        const uint32_t s0 = sbase + (uint32_t)buf * CFG::STAGE * 2u;
        #pragma unroll
        for (int t = 0; t < 4; t++)
            CP_ASYNC16(s0 + (uint32_t)(ar[t] * LDAH2 + ac[t]) * 2u,
                       A + (size_t)(bm + ar[t]) * K + k0 + ac[t]);
        const uint32_t s1 = s0 + AH_STAGE2 * 2u;
        #pragma unroll
        for (int t = 0; t < CFG::TBH; t++)
            CP_ASYNC16(s1 + (uint32_t)(br[t] * CFG::LDBH_ + bc[t]) * 2u,
                       B + (size_t)(k0 + br[t]) * N + bn + bc[t]);
        CP_COMMIT();
    };

    issue(0, 0);
    issue(1, 1);

    const int l15 = lane & 15, lhi = lane >> 4;
    const uint32_t aAddrBase = (uint32_t)(((wm * 32 + l15) * LDAH2 + lhi * 8) * 2);
    const uint32_t bAddrBase = (uint32_t)((l15 * CFG::LDBH_ + wn * (NJ * 8) + lhi * 8) * 2);

    for (int i = 0; i < niter; i++) {
        if (i + 1 < niter) { CP_WAIT(1); } else { CP_WAIT(0); }
        __syncthreads();
        if (i + 2 < niter) issue(i + 2, (i + 2) % 3);

        const uint32_t sA = sbase + (uint32_t)((i % 3) * CFG::STAGE) * 2u;
        const uint32_t sB = sA + AH_STAGE2 * 2u;

        #pragma unroll
        for (int kk = 0; kk < 4; kk++) {
            uint32_t a[2][4];
            #pragma unroll
            for (int mi = 0; mi < 2; mi++)
                LDMX4(a[mi], sA + aAddrBase + (uint32_t)((mi * 16 * LDAH2 + kk * 16) * 2));
            #pragma unroll
            for (int nj2 = 0; nj2 < NJ / 2; nj2++) {
                uint32_t bf[4];
                LDMX4T(bf, sB + bAddrBase + (uint32_t)((kk * 16 * CFG::LDBH_ + nj2 * 16) * 2));
                #pragma unroll
                for (int hh = 0; hh < 2; hh++) {
                    #pragma unroll
                    for (int mi = 0; mi < 2; mi++)
                        mma_f16(acc[mi][nj2 * 2 + hh], a[mi], bf[hh * 2], bf[hh * 2 + 1]);
                }
            }
        }
    }

    #pragma unroll
    for (int mi = 0; mi < 2; mi++) {
        const int row0 = bm + wm * 32 + mi * 16 + (lane >> 2);
        #pragma unroll
        for (int nj = 0; nj < NJ; nj++) {
            const int col0 = bn + wn * (NJ * 8) + nj * 8 + (lane & 3) * 2;
            const float b0 = bias[col0], b1 = bias[col0 + 1];
            #pragma unroll
            for (int hh = 0; hh < 2; hh++) {
                const int row = row0 + hh * 8;
                float v0 = acc[mi][nj][hh * 2 + 0] + b0;
                float v1 = acc[mi][nj][hh * 2 + 1] + b1;
                size_t g = (size_t)row * N + col0;
                if (EPI == 0) {
                    *(__half2*)((__half*)Cout + g) = __floats2half2_rn(v0, v1);
                } else if (EPI == 1) {
                    *(__half2*)((__half*)Cout + g) =
                        __floats2half2_rn(gelu_new(v0), gelu_new(v1));
                } else {
                    float2 rv = *(const float2*)(R + g);
                    float2 o; o.x = v0 + rv.x; o.y = v1 + rv.y;
                    *(float2*)((float*)Cout + g) = o;
                }
            }
        }
    }
}

// ---------------- layernorm: 4 rows/block, 64 thr/row, float4, 1 pass -------
__global__ __launch_bounds__(256)
void ln4_h(const float* __restrict__ in, const float* __restrict__ w,
           const float* __restrict__ b, __half* __restrict__ out) {
    const int tid = threadIdx.x;
    const int rloc = tid >> 6;
    const int t    = tid & 63;
    const int row  = blockIdx.x * 4 + rloc;
    const int lane = tid & 31;
    const int wIdx = (tid >> 5) & 1;

    const float4* xp = (const float4*)(in + (size_t)row * DM);
    float4 v[3];
    float s = 0.f, ss = 0.f;
    #pragma unroll
    for (int k = 0; k < 3; k++) {
        v[k] = xp[t + k * 64];
        s  += v[k].x + v[k].y + v[k].z + v[k].w;
        ss += v[k].x * v[k].x + v[k].y * v[k].y + v[k].z * v[k].z + v[k].w * v[k].w;
    }
    #pragma unroll
    for (int o = 16; o; o >>= 1) {
        s  += __shfl_xor_sync(0xffffffffu, s,  o);
        ss += __shfl_xor_sync(0xffffffffu, ss, o);
    }
    __shared__ float sb[4][2], qb[4][2];
    if (lane == 0) { sb[rloc][wIdx] = s; qb[rloc][wIdx] = ss; }
    __syncthreads();
    s  = sb[rloc][0] + sb[rloc][1];
    ss = qb[rloc][0] + qb[rloc][1];
    float mean = s * (1.f / DM);
    float inv  = rsqrtf(ss * (1.f / DM) - mean * mean + 1e-5f);

    const float4* wp = (const float4*)w;
    const float4* bp = (const float4*)b;
    __half2* op = (__half2*)(out + (size_t)row * DM);
    #pragma unroll
    for (int k = 0; k < 3; k++) {
        float4 wv = wp[t + k * 64], bv = bp[t + k * 64];
        float o0 = (v[k].x - mean) * inv * wv.x + bv.x;
        float o1 = (v[k].y - mean) * inv * wv.y + bv.y;
        float o2 = (v[k].z - mean) * inv * wv.z + bv.z;
        float o3 = (v[k].w - mean) * inv * wv.w + bv.w;
        op[(t + k * 64) * 2]     = __floats2half2_rn(o0, o1);
        op[(t + k * 64) * 2 + 1] = __floats2half2_rn(o2, o3);
    }
}

// ---------------- merged weight prep (vectorized) ----------------------------
__global__ void prep_weights(const float* __restrict__ WQ, const float* __restrict__ WK,
                             const float* __restrict__ WV, const float* __restrict__ WO,
                             const float* __restrict__ Win, const float* __restrict__ Wout,
                             const float* __restrict__ bQ, const float* __restrict__ bK,
                             const float* __restrict__ bV,
                             __half* __restrict__ Wqkv, __half* __restrict__ Wo_h,
                             __half* __restrict__ Win_h, __half* __restrict__ Wout_h,
                             float* __restrict__ bias) {
    int idx = blockIdx.x * 256 + threadIdx.x;
    if (idx < DM * DM) {
        float4 wi = ((const float4*)Win)[idx];
        float4 wo = ((const float4*)Wout)[idx];
        ((__half2*)Win_h)[idx * 2]      = __floats2half2_rn(wi.x, wi.y);
        ((__half2*)Win_h)[idx * 2 + 1]  = __floats2half2_rn(wi.z, wi.w);
        ((__half2*)Wout_h)[idx * 2]     = __floats2half2_rn(wo.x, wo.y);
        ((__half2*)Wout_h)[idx * 2 + 1] = __floats2half2_rn(wo.z, wo.w);
        Wo_h[idx] = __float2half_rn(WO[idx]);
        int k = idx / DM, n = idx % DM;
        int h = n >> 6, e = n & 63;
        int src = h * (DM * DH) + k * DH + e;
        Wqkv[(size_t)k * QKVN + n]          = __float2half_rn(WQ[src]);
        Wqkv[(size_t)k * QKVN + DM + n]     = __float2half_rn(WK[src]);
        Wqkv[(size_t)k * QKVN + 2 * DM + n] = __float2half_rn(WV[src]);
    }
    if (idx < DM) {
        bias[idx]          = bQ[idx];
        bias[DM + idx]     = bK[idx];
        bias[2 * DM + idx] = bV[idx];
    }
}

// ============== flash attention via fp16 mma.sync (causal, cp.async) ========
// 128 thr / 4 warps; Q tile 64 rows (16/warp); K/V tile 64 keys, 2-buffer ring;
// 1 sync per K-tile; log2-domain softmax. 4 CTAs/SM (46 KB smem).
#define LDH 72
#define AK_OFF (64*LDH)
#define AV_OFF (AK_OFF + 2*64*LDH)
#define ATTNH_SMEM ((AV_OFF + 2*64*LDH)*2)   /* 320*72*2 = 46080 B */

__global__ __launch_bounds__(128, 4)
void attn_h(const __half* __restrict__ QKV, __half* __restrict__ Z) {
    extern __shared__ __half smh[];
    const uint32_t sbase = smem_u32(smh);

    const int tid = threadIdx.x, lane = tid & 31, wid = tid >> 5;
    const int r = lane >> 2, c = lane & 3;
    const int l15 = lane & 15, lhi = lane >> 4;
    const int qt = gridDim.x - 1 - blockIdx.x;       // heavy blocks first
    const int qt0 = qt * 64;
    const int h = blockIdx.y, b = blockIdx.z;

    const __half* qbase = QKV + ((size_t)(b * SEQ + qt0)) * QKVN + h * DH;
    const __half* kbase = QKV + ((size_t)b * SEQ) * QKVN + DM     + h * DH;
    const __half* vbase = QKV + ((size_t)b * SEQ) * QKVN + 2 * DM + h * DH;

    const int ntiles = qt0 / 64 + 1;

    auto issue_kv = [&](int kt, int buf) {
        const __half* kb = kbase + (size_t)(kt * 64) * QKVN;
        const __half* vb = vbase + (size_t)(kt * 64) * QKVN;
        const uint32_t ks = sbase + (uint32_t)(AK_OFF + buf * 64 * LDH) * 2u;
        const uint32_t vs = sbase + (uint32_t)(AV_OFF + buf * 64 * LDH) * 2u;
        #pragma unroll
        for (int t = 0; t < 4; t++) {
            int ci = tid + t * 128;                 // 0..511
            int row = ci >> 3, ch = (ci & 7) * 8;
            CP_ASYNC16(ks + (uint32_t)(row * LDH + ch) * 2u,
                       kb + (size_t)row * QKVN + ch);
            CP_ASYNC16(vs + (uint32_t)(row * LDH + ch) * 2u,
                       vb + (size_t)row * QKVN + ch);
        }
        CP_COMMIT();
    };

    {   // group 0: Q (64 rows) + KV tile 0 -> buf 0
        #pragma unroll
        for (int t = 0; t < 4; t++) {
            int ci = tid + t * 128;                 // 0..511
            int row = ci >> 3, ch = (ci & 7) * 8;
            CP_ASYNC16(sbase + (uint32_t)(row * LDH + ch) * 2u,
                       qbase + (size_t)row * QKVN + ch);
        }
        const uint32_t ks = sbase + (uint32_t)AK_OFF * 2u;
        const uint32_t vs = sbase + (uint32_t)AV_OFF * 2u;
        #pragma unroll
        for (int t = 0; t < 4; t++) {
            int ci = tid + t * 128;
            int row = ci >> 3, ch = (ci & 7) * 8;
            CP_ASYNC16(ks + (uint32_t)(row * LDH + ch) * 2u,
                       kbase + (size_t)row * QKVN + ch);
            CP_ASYNC16(vs + (uint32_t)(row * LDH + ch) * 2u,
                       vbase + (size_t)row * QKVN + ch);
        }
        CP_COMMIT();
    }

    float o[8][4];
    #pragma unroll
    for (int nj = 0; nj < 8; nj++)
        #pragma unroll
        for (int t = 0; t < 4; t++) o[nj][t] = 0.f;
    float m0 = -1e30f, m1 = -1e30f, l0 = 0.f, l1 = 0.f;

    const int q0g = qt0 + wid * 16 + r;
    const int qmax_warp = qt0 + wid * 16 + 15;

    uint32_t qa[4][4];

    for (int kt = 0; kt < ntiles; kt++) {
        CP_WAIT(0);                 // tile kt (sole outstanding group) ready
        __syncthreads();            // all warps done with buffer (kt+1)&1 from kt-1
        if (kt + 1 < ntiles) issue_kv(kt + 1, (kt + 1) & 1);

        if (kt == 0) {
            const uint32_t qaddr = sbase + (uint32_t)(((wid * 16 + l15) * LDH + lhi * 8) * 2);
            __half2 sc = __floats2half2_rn(0.18033688f, 0.18033688f);
            #pragma unroll
            for (int kk = 0; kk < 4; kk++) {
                LDMX4(qa[kk], qaddr + (uint32_t)(kk * 16 * 2));
                #pragma unroll
                for (int j = 0; j < 4; j++) {
                    __half2 v = *reinterpret_cast<__half2*>(&qa[kk][j]);
                    v = __hmul2(v, sc);
                    qa[kk][j] = *reinterpret_cast<uint32_t*>(&v);
                }
            }
        }

        if (kt * 64 <= qmax_warp) {
            const int buf = kt & 1;
            const uint32_t Kb = sbase + (uint32_t)(AK_OFF + buf * 64 * LDH) * 2u;
            const uint32_t Vb = sbase + (uint32_t)(AV_OFF + buf * 64 * LDH) * 2u;

            float s[8][4];
            #pragma unroll
            for (int nj = 0; nj < 8; nj++)
                #pragma unroll
                for (int t = 0; t < 4; t++) s[nj][t] = 0.f;

            const int g = lane >> 3;
            #pragma unroll
            for (int g2 = 0; g2 < 4; g2++) {
                const uint32_t rowb = Kb +
                    (uint32_t)(((16 * g2 + (g >> 1) * 8 + (lane & 7)) * LDH) * 2);
                #pragma unroll
                for (int kk = 0; kk < 4; kk++) {
                    uint32_t bk[4];
                    LDMX4(bk, rowb + (uint32_t)((kk * 16 + (g & 1) * 8) * 2));
                    mma_f16(s[2 * g2],     qa[kk], bk[0], bk[1]);
                    mma_f16(s[2 * g2 + 1], qa[kk], bk[2], bk[3]);
                }
            }

            if (kt * 64 + 63 > qt0 + wid * 16) {
                #pragma unroll
                for (int nj = 0; nj < 8; nj++) {
                    int k0c = kt * 64 + nj * 8 + c * 2;
                    if (k0c     > q0g)     s[nj][0] = -1e30f;
                    if (k0c + 1 > q0g)     s[nj][1] = -1e30f;
                    if (k0c     > q0g + 8) s[nj][2] = -1e30f;
                    if (k0c + 1 > q0g + 8) s[nj][3] = -1e30f;
                }
            }

            float mt0 = -1e30f, mt1 = -1e30f;
            #pragma unroll
            for (int nj = 0; nj < 8; nj++) {
                mt0 = fmaxf(mt0, fmaxf(s[nj][0], s[nj][1]));
                mt1 = fmaxf(mt1, fmaxf(s[nj][2], s[nj][3]));
            }
            mt0 = fmaxf(mt0, __shfl_xor_sync(0xffffffffu, mt0, 1));
            mt0 = fmaxf(mt0, __shfl_xor_sync(0xffffffffu, mt0, 2));
            mt1 = fmaxf(mt1, __shfl_xor_sync(0xffffffffu, mt1, 1));
            mt1 = fmaxf(mt1, __shfl_xor_sync(0xffffffffu, mt1, 2));

            float mn0 = fmaxf(m0, mt0), mn1 = fmaxf(m1, mt1);
            float cr0 = ex2f(m0 - mn0), cr1 = ex2f(m1 - mn1);
            float ls0 = 0.f, ls1 = 0.f;
            #pragma unroll
            for (int nj = 0; nj < 8; nj++) {
                s[nj][0] = ex2f(s[nj][0] - mn0);
                s[nj][1] = ex2f(s[nj][1] - mn0);
                s[nj][2] = ex2f(s[nj][2] - mn1);
                s[nj][3] = ex2f(s[nj][3] - mn1);
                ls0 += s[nj][0] + s[nj][1];
                ls1 += s[nj][2] + s[nj][3];
            }
            ls0 += __shfl_xor_sync(0xffffffffu, ls0, 1);
            ls0 += __shfl_xor_sync(0xffffffffu, ls0, 2);
            ls1 += __shfl_xor_sync(0xffffffffu, ls1, 1);
            ls1 += __shfl_xor_sync(0xffffffffu, ls1, 2);
            l0 = l0 * cr0 + ls0;
            l1 = l1 * cr1 + ls1;
            m0 = mn0; m1 = mn1;
            #pragma unroll
            for (int nj = 0; nj < 8; nj++) {
                o[nj][0] *= cr0; o[nj][1] *= cr0;
                o[nj][2] *= cr1; o[nj][3] *= cr1;
            }

            #pragma unroll
            for (int kk = 0; kk < 4; kk++) {
                uint32_t pa[4];
                pa[0] = pack_h2(s[2 * kk][0],     s[2 * kk][1]);
                pa[1] = pack_h2(s[2 * kk][2],     s[2 * kk][3]);
                pa[2] = pack_h2(s[2 * kk + 1][0], s[2 * kk + 1][1]);
                pa[3] = pack_h2(s[2 * kk + 1][2], s[2 * kk + 1][3]);
                const uint32_t rowb = Vb + (uint32_t)(((kk * 16 + l15) * LDH + lhi * 8) * 2);
                #pragma unroll
                for (int nj2 = 0; nj2 < 4; nj2++) {
                    uint32_t bv[4];
                    LDMX4T(bv, rowb + (uint32_t)((nj2 * 16) * 2));
                    mma_f16(o[2 * nj2],     pa, bv[0], bv[1]);
                    mma_f16(o[2 * nj2 + 1], pa, bv[2], bv[3]);
                }
            }
        }
    }

    float inv0 = 1.f / l0, inv1 = 1.f / l1;
    #pragma unroll
    for (int nj = 0; nj < 8; nj++) {
        int col = h * DH + nj * 8 + c * 2;
        size_t g0 = (size_t)(b * SEQ + q0g) * DM + col;
        size_t g1 = (size_t)(b * SEQ + q0g + 8) * DM + col;
        *(__half2*)(Z + g0) = __floats2half2_rn(o[nj][0] * inv0, o[nj][1] * inv0);
        *(__half2*)(Z + g1) = __floats2half2_rn(o[nj][2] * inv1, o[nj][3] * inv1);
    }
}

// ---------------- launch -----------------------------------------------------
extern "C" void kernel_launch(void* const* d_in, const int* in_sizes, int n_in,
                              void* d_out, int out_size) {
    const float* resid_pre = (const float*)d_in[0];
    const float* W_Q   = (const float*)d_in[1];
    const float* b_Q   = (const float*)d_in[2];
    const float* W_K   = (const float*)d_in[3];
    const float* b_K   = (const float*)d_in[4];
    const float* W_V   = (const float*)d_in[5];
    const float* b_V   = (const float*)d_in[6];
    const float* W_O   = (const float*)d_in[7];
    const float* b_O   = (const float*)d_in[8];
    const float* ln1_w = (const float*)d_in[9];
    const float* ln1_b = (const float*)d_in[10];
    const float* ln2_w = (const float*)d_in[11];
    const float* ln2_b = (const float*)d_in[12];
    const float* W_in  = (const float*)d_in[13];
    const float* b_in  = (const float*)d_in[14];
    const float* W_out = (const float*)d_in[15];
    const float* b_out = (const float*)d_in[16];
    float* out = (float*)d_out;

    float *pbqkv, *pmid;
    __half *px_h, *pwqkv_h, *pqkv_h, *pz_h, *py_h, *ph_h, *pwo_h, *pwin_h, *pwout_h;
    cudaGetSymbolAddress((void**)&px_h,    g_x_h);
    cudaGetSymbolAddress((void**)&pwqkv_h, g_wqkv_h);
    cudaGetSymbolAddress((void**)&pbqkv,   g_bqkv);
    cudaGetSymbolAddress((void**)&pqkv_h,  g_qkv_h);
    cudaGetSymbolAddress((void**)&pz_h,    g_z_h);
    cudaGetSymbolAddress((void**)&pmid,    g_mid);
    cudaGetSymbolAddress((void**)&py_h,    g_y_h);
    cudaGetSymbolAddress((void**)&ph_h,    g_h_h);
    cudaGetSymbolAddress((void**)&pwo_h,   g_wo_h);
    cudaGetSymbolAddress((void**)&pwin_h,  g_win_h);
    cudaGetSymbolAddress((void**)&pwout_h, g_wout_h);

    cudaFuncSetAttribute((const void*)gemm_h<0,8>, cudaFuncAttributeMaxDynamicSharedMemorySize, GemmHCfg<8>::SMEM);
    cudaFuncSetAttribute((const void*)gemm_h<1,8>, cudaFuncAttributeMaxDynamicSharedMemorySize, GemmHCfg<8>::SMEM);
    cudaFuncSetAttribute((const void*)gemm_h<2,4>, cudaFuncAttributeMaxDynamicSharedMemorySize, GemmHCfg<4>::SMEM);
    cudaFuncSetAttribute((const void*)attn_h,      cudaFuncAttributeMaxDynamicSharedMemorySize, ATTNH_SMEM);

    prep_weights<<<(DM * DM + 255) / 256, 256>>>(
        W_Q, W_K, W_V, W_O, W_in, W_out, b_Q, b_K, b_V,
        pwqkv_h, pwo_h, pwin_h, pwout_h, pbqkv);

    ln4_h<<<ROWS / 4, 256>>>(resid_pre, ln1_w, ln1_b, px_h);
    gemm_h<0,8><<<dim3(QKVN / 128, ROWS / 128), 256, GemmHCfg<8>::SMEM>>>(
        px_h, pwqkv_h, pbqkv, nullptr, pqkv_h, ROWS, QKVN, DM);
    attn_h<<<dim3(SEQ / 64, NH, BATCH), 128, ATTNH_SMEM>>>(pqkv_h, pz_h);
    gemm_h<2,4><<<dim3(DM / 64, ROWS / 128), 256, GemmHCfg<4>::SMEM>>>(
        pz_h, pwo_h, b_O, resid_pre, pmid, ROWS, DM, DM);
    ln4_h<<<ROWS / 4, 256>>>(pmid, ln2_w, ln2_b, py_h);
    gemm_h<1,8><<<dim3(DMLP / 128, ROWS / 128), 256, GemmHCfg<8>::SMEM>>>(
        py_h, pwin_h, b_in, nullptr, ph_h, ROWS, DMLP, DM);
    gemm_h<2,4><<<dim3(DM / 64, ROWS / 128), 256, GemmHCfg<4>::SMEM>>>(
        ph_h, pwout_h, b_out, pmid, out, ROWS, DM, DMLP);
}